// round 12
// baseline (speedup 1.0000x reference)
#include <cuda_runtime.h>
#include <cuda_fp16.h>
#include <math.h>

#define N_NODES 50000
#define N_EDGES 1600000
#define D_IN    128
#define D_HID   50
#define D_OUT   10
#define STRIDE  64   // fp32 row stride (floats) for P0..P4
#define HSTRIDE 32   // fp16 row stride (half2 units) = 128 bytes
#define CAP     128  // bucket capacity per row (17-sigma headroom over mean 32)

// ---------------- static scratch ----------------
__device__ float g_P [(size_t)5 * N_NODES * STRIDE];              // P0..P4 fp32
__device__ float g_Pb[(size_t)2 * N_NODES * STRIDE];              // K-half-B partials: [0]=P3b, [1]=P4b
__device__ __align__(128) __half2 g_P4s[(size_t)N_NODES * HSTRIDE];  // D*P4
__device__ __align__(128) __half2 g_b3s[(size_t)N_NODES * HSTRIDE];  // D*b3
__device__ __align__(128) __half2 g_b3r[(size_t)N_NODES * HSTRIDE];  // b3 real
__device__ __align__(128) __half2 g_b2s[(size_t)N_NODES * HSTRIDE];
__device__ __align__(128) __half2 g_b2r[(size_t)N_NODES * HSTRIDE];
__device__ __align__(128) __half2 g_b1s[(size_t)N_NODES * HSTRIDE];
__device__ int   g_cursor[N_NODES];                                // degree counters
__device__ float g_dinv  [N_NODES];
__device__ __align__(16) unsigned short g_bucket[(size_t)N_NODES * CAP];
__device__ int   g_is64;

// ---------------- init: zero cursors + dtype detect ----------------
__global__ void init_kernel(const int* __restrict__ ei32) {
    int i = blockIdx.x * blockDim.x + threadIdx.x;
    if (i < N_NODES) g_cursor[i] = 0;
    if (blockIdx.x == 0) {
        __shared__ int nz;
        if (threadIdx.x == 0) nz = 0;
        __syncthreads();
        // int64 edge_index with values<50000 has all-zero high words
        if (ei32[2 * threadIdx.x + 1] != 0) atomicExch(&nz, 1);
        __syncthreads();
        if (threadIdx.x == 0) g_is64 = (nz == 0) ? 1 : 0;
    }
}

// ---------------- scatter: single-pass bucket CSR (cols only), 2 edges/thread ----
__global__ void scatter_kernel(const void* __restrict__ ei) {
    int t = blockIdx.x * blockDim.x + threadIdx.x;
    if (t >= N_EDGES / 2) return;
    int r0, r1, c0, c1;
    if (g_is64) {
        longlong2 rv = __ldg((const longlong2*)ei + t);
        longlong2 cv = __ldg((const longlong2*)ei + (N_EDGES / 2) + t);
        r0 = (int)rv.x; r1 = (int)rv.y; c0 = (int)cv.x; c1 = (int)cv.y;
    } else {
        int2 rv = __ldg((const int2*)ei + t);
        int2 cv = __ldg((const int2*)ei + (N_EDGES / 2) + t);
        r0 = rv.x; r1 = rv.y; c0 = cv.x; c1 = cv.y;
    }
    int p0 = atomicAdd(&g_cursor[r0], 1);
    if (p0 < CAP) g_bucket[(size_t)r0 * CAP + p0] = (unsigned short)c0;
    int p1 = atomicAdd(&g_cursor[r1], 1);
    if (p1 < CAP) g_bucket[(size_t)r1 * CAP + p1] = (unsigned short)c1;
}

// ---------------- dinv from the post-scatter cursors ----------------
__global__ void dinv_kernel() {
    int n = blockIdx.x * blockDim.x + threadIdx.x;
    if (n >= N_NODES) return;
    int d = g_cursor[n];
    g_dinv[n] = (d > 0) ? rsqrtf((float)d) : 0.0f;
}

// ---------------- combine P4 halves -> fp32 P4 + fp16 D*P4, warp per row ---------
__global__ void __launch_bounds__(256) scaleP4_kernel() {
    int gw = (blockIdx.x * blockDim.x + threadIdx.x) >> 5;
    int lane = threadIdx.x & 31;
    if (gw >= N_NODES || lane >= 25) return;
    float di = __ldg(&g_dinv[gw]);
    float2* p4 = (float2*)(g_P + ((size_t)4 * N_NODES + gw) * STRIDE) + lane;
    const float2* p4b = (const float2*)(g_Pb + ((size_t)1 * N_NODES + gw) * STRIDE) + lane;
    float2 a = __ldg((const float2*)p4);
    float2 b = __ldg(p4b);
    float sx = a.x + b.x, sy = a.y + b.y;
    *p4 = make_float2(sx, sy);                       // combined fp32 for prop2's sub
    g_P4s[(size_t)gw * HSTRIDE + lane] = __floats2half2_rn(di * sx, di * sy);
}

// ---------------- f32x2 helpers ----------------
__device__ __forceinline__ unsigned long long pack2(float lo, float hi) {
    unsigned long long r;
    asm("mov.b64 %0, {%1, %2};" : "=l"(r) : "f"(lo), "f"(hi));
    return r;
}
__device__ __forceinline__ void unpack2(unsigned long long v, float& lo, float& hi) {
    asm("mov.b64 {%0, %1}, %2;" : "=f"(lo), "=f"(hi) : "l"(v));
}
#define FMA2(acc, a, b) asm("fma.rn.f32x2 %0, %1, %2, %0;" : "+l"(acc) : "l"(a), "l"(b))

// ---------------- full-K projection: P_k = x @ W_k (fp32), 2 nodes/thread --------
__global__ void __launch_bounds__(128) proj_kernel(const float* __restrict__ x,
                                                   const float* __restrict__ cheb_w,
                                                   int k_offset) {
    __shared__ __align__(16) float Wsm[D_IN * 52];
    int tid = threadIdx.x;
    int k = blockIdx.y + k_offset;
    const float* W = cheb_w + (size_t)k * D_IN * D_HID;
    #pragma unroll 1
    for (int o = 0; o < D_HID; o++) Wsm[tid * 52 + o] = W[tid * D_HID + o];
    Wsm[tid * 52 + 50] = 0.0f;
    Wsm[tid * 52 + 51] = 0.0f;
    __syncthreads();

    int n0 = blockIdx.x * 256 + tid;
    int n1 = n0 + 128;
    bool v0 = n0 < N_NODES;
    bool v1 = n1 < N_NODES;

    unsigned long long acc0[26], acc1[26];
    #pragma unroll
    for (int p = 0; p < 26; p++) { acc0[p] = 0ull; acc1[p] = 0ull; }

    const float4* A0 = (const float4*)(x + (size_t)n0 * D_IN);
    const float4* A1 = (const float4*)(x + (size_t)n1 * D_IN);
    float4 z4 = make_float4(0.f, 0.f, 0.f, 0.f);
    float4 a0 = v0 ? __ldg(A0) : z4;
    float4 a1 = v1 ? __ldg(A1) : z4;

    #pragma unroll 1
    for (int ic = 0; ic < 32; ic++) {
        float4 a0n = z4, a1n = z4;
        if (ic < 31) {
            if (v0) a0n = __ldg(A0 + ic + 1);
            if (v1) a1n = __ldg(A1 + ic + 1);
        }
        float av0[4] = {a0.x, a0.y, a0.z, a0.w};
        float av1[4] = {a1.x, a1.y, a1.z, a1.w};
        #pragma unroll
        for (int j = 0; j < 4; j++) {
            unsigned long long a0p = pack2(av0[j], av0[j]);
            unsigned long long a1p = pack2(av1[j], av1[j]);
            const float4* wrow = (const float4*)(Wsm + (ic * 4 + j) * 52);
            #pragma unroll
            for (int q = 0; q < 13; q++) {
                float4 wv = wrow[q];
                unsigned long long w01 = pack2(wv.x, wv.y);
                unsigned long long w23 = pack2(wv.z, wv.w);
                FMA2(acc0[2 * q],     w01, a0p);
                FMA2(acc0[2 * q + 1], w23, a0p);
                FMA2(acc1[2 * q],     w01, a1p);
                FMA2(acc1[2 * q + 1], w23, a1p);
            }
        }
        a0 = a0n; a1 = a1n;
    }

    #pragma unroll
    for (int which = 0; which < 2; which++) {
        bool v = which ? v1 : v0;
        int n = which ? n1 : n0;
        unsigned long long* acc = which ? acc1 : acc0;
        if (!v) continue;
        float* dst = g_P + ((size_t)k * N_NODES + n) * STRIDE;
        #pragma unroll
        for (int q = 0; q < 12; q++) {
            float x0, x1, x2, x3;
            unpack2(acc[2 * q], x0, x1);
            unpack2(acc[2 * q + 1], x2, x3);
            ((float4*)dst)[q] = make_float4(x0, x1, x2, x3);
        }
        float x0, x1; unpack2(acc[24], x0, x1);
        ((float2*)dst)[24] = make_float2(x0, x1);
    }
}

// ---------------- half-K partial projection (for k=3,4): halves serial chain -----
// Computes x[:, 64h:64h+64] @ W_k[64h:64h+64, :] into dst (fp32, STRIDE rows).
__global__ void __launch_bounds__(128) proj_half_kernel(const float* __restrict__ x,
                                                        const float* __restrict__ cheb_w,
                                                        int k, int half,
                                                        float* __restrict__ dst_base) {
    __shared__ __align__(16) float Wsm[64 * 52];
    int tid = threadIdx.x;
    const float* W = cheb_w + ((size_t)k * D_IN + half * 64) * D_HID;
    if (tid < 64) {
        #pragma unroll 1
        for (int o = 0; o < D_HID; o++) Wsm[tid * 52 + o] = W[tid * D_HID + o];
        Wsm[tid * 52 + 50] = 0.0f;
        Wsm[tid * 52 + 51] = 0.0f;
    }
    __syncthreads();

    int n0 = blockIdx.x * 256 + tid;
    int n1 = n0 + 128;
    bool v0 = n0 < N_NODES;
    bool v1 = n1 < N_NODES;

    unsigned long long acc0[26], acc1[26];
    #pragma unroll
    for (int p = 0; p < 26; p++) { acc0[p] = 0ull; acc1[p] = 0ull; }

    const float4* A0 = (const float4*)(x + (size_t)n0 * D_IN + half * 64);
    const float4* A1 = (const float4*)(x + (size_t)n1 * D_IN + half * 64);
    float4 z4 = make_float4(0.f, 0.f, 0.f, 0.f);
    float4 a0 = v0 ? __ldg(A0) : z4;
    float4 a1 = v1 ? __ldg(A1) : z4;

    #pragma unroll 1
    for (int ic = 0; ic < 16; ic++) {
        float4 a0n = z4, a1n = z4;
        if (ic < 15) {
            if (v0) a0n = __ldg(A0 + ic + 1);
            if (v1) a1n = __ldg(A1 + ic + 1);
        }
        float av0[4] = {a0.x, a0.y, a0.z, a0.w};
        float av1[4] = {a1.x, a1.y, a1.z, a1.w};
        #pragma unroll
        for (int j = 0; j < 4; j++) {
            unsigned long long a0p = pack2(av0[j], av0[j]);
            unsigned long long a1p = pack2(av1[j], av1[j]);
            const float4* wrow = (const float4*)(Wsm + (ic * 4 + j) * 52);
            #pragma unroll
            for (int q = 0; q < 13; q++) {
                float4 wv = wrow[q];
                unsigned long long w01 = pack2(wv.x, wv.y);
                unsigned long long w23 = pack2(wv.z, wv.w);
                FMA2(acc0[2 * q],     w01, a0p);
                FMA2(acc0[2 * q + 1], w23, a0p);
                FMA2(acc1[2 * q],     w01, a1p);
                FMA2(acc1[2 * q + 1], w23, a1p);
            }
        }
        a0 = a0n; a1 = a1n;
    }

    #pragma unroll
    for (int which = 0; which < 2; which++) {
        bool v = which ? v1 : v0;
        int n = which ? n1 : n0;
        unsigned long long* acc = which ? acc1 : acc0;
        if (!v) continue;
        float* dst = dst_base + (size_t)n * STRIDE;
        #pragma unroll
        for (int q = 0; q < 12; q++) {
            float x0, x1, x2, x3;
            unpack2(acc[2 * q], x0, x1);
            unpack2(acc[2 * q + 1], x2, x3);
            ((float4*)dst)[q] = make_float4(x0, x1, x2, x3);
        }
        float x0, x1; unpack2(acc[24], x0, x1);
        ((float2*)dst)[24] = make_float2(x0, x1);
    }
}

// ---------------- weightless gather accumulate: uint16 bucket, aligned bursts -----
__device__ __forceinline__ void row_sum_h(const __half2* __restrict__ src,
                                          const unsigned short* __restrict__ row,
                                          int deg, bool act, int lane,
                                          float& Sx, float& Sy) {
    float ax0 = 0.f, ay0 = 0.f, ax1 = 0.f, ay1 = 0.f;
    int i = 0;
    #pragma unroll 1
    for (; i + 8 <= deg; i += 8) {
        uint4 cp = __ldg((const uint4*)(row + i));       // 8 cols, 16B aligned
        unsigned c[8];
        c[0] = cp.x & 0xffffu; c[1] = cp.x >> 16;
        c[2] = cp.y & 0xffffu; c[3] = cp.y >> 16;
        c[4] = cp.z & 0xffffu; c[5] = cp.z >> 16;
        c[6] = cp.w & 0xffffu; c[7] = cp.w >> 16;
        if (act) {
            __half2 v[8];
            #pragma unroll
            for (int u = 0; u < 8; u++)
                v[u] = __ldcg((__half2*)(src + (size_t)c[u] * HSTRIDE + lane));
            #pragma unroll
            for (int u = 0; u < 8; u++) {
                float2 vf = __half22float2(v[u]);
                if (u & 1) { ax1 += vf.x; ay1 += vf.y; }
                else       { ax0 += vf.x; ay0 += vf.y; }
            }
        }
    }
    if (deg - i >= 4) {
        uint2 cp = __ldg((const uint2*)(row + i));       // 8B aligned
        unsigned c[4];
        c[0] = cp.x & 0xffffu; c[1] = cp.x >> 16;
        c[2] = cp.y & 0xffffu; c[3] = cp.y >> 16;
        if (act) {
            #pragma unroll
            for (int u = 0; u < 4; u++) {
                float2 vf = __half22float2(
                    __ldcg((__half2*)(src + (size_t)c[u] * HSTRIDE + lane)));
                if (u & 1) { ax1 += vf.x; ay1 += vf.y; }
                else       { ax0 += vf.x; ay0 += vf.y; }
            }
        }
        i += 4;
    }
    if (deg - i >= 2) {
        unsigned cp = __ldg((const unsigned*)(row + i)); // 4B aligned
        unsigned c0 = cp & 0xffffu, c1 = cp >> 16;
        if (act) {
            float2 v0 = __half22float2(__ldcg((__half2*)(src + (size_t)c0 * HSTRIDE + lane)));
            float2 v1 = __half22float2(__ldcg((__half2*)(src + (size_t)c1 * HSTRIDE + lane)));
            ax0 += v0.x; ay0 += v0.y;
            ax1 += v1.x; ay1 += v1.y;
        }
        i += 2;
    }
    if (i < deg) {
        unsigned c = __ldg(row + i);
        if (act) {
            float2 v = __half22float2(__ldcg((__half2*)(src + (size_t)c * HSTRIDE + lane)));
            ax0 += v.x; ay0 += v.y;
        }
    }
    Sx = ax0 + ax1;
    Sy = ay0 + ay1;
}

// ------- Clenshaw prop: real = P (+Padd) - scale*dinv*S - sub; scaled = dinv*real
__global__ void __launch_bounds__(256) prop_b(const __half2* __restrict__ src,
                                              const float* __restrict__ P,
                                              const float* __restrict__ Padd,
                                              const __half2* __restrict__ subH,
                                              const float* __restrict__ subF,
                                              float scale,
                                              __half2* __restrict__ dstR,
                                              __half2* __restrict__ dstS) {
    int gw = (blockIdx.x * blockDim.x + threadIdx.x) >> 5;
    int lane = threadIdx.x & 31;
    if (gw >= N_NODES) return;
    int deg = __ldg(&g_cursor[gw]);
    if (deg > CAP) deg = CAP;
    const unsigned short* row = g_bucket + (size_t)gw * CAP;
    const bool act = lane < 25;
    float Sx, Sy;
    row_sum_h(src, row, deg, act, lane, Sx, Sy);

    if (act) {
        float di = __ldg(&g_dinv[gw]);
        float2 p = __ldg((const float2*)P + (size_t)gw * (STRIDE / 2) + lane);
        float sdi = scale * di;
        float rx = p.x - sdi * Sx;
        float ry = p.y - sdi * Sy;
        if (Padd) {
            float2 pa = __ldg((const float2*)Padd + (size_t)gw * (STRIDE / 2) + lane);
            rx += pa.x; ry += pa.y;
        }
        if (subH) {
            float2 sb = __half22float2(__ldg(subH + (size_t)gw * HSTRIDE + lane));
            rx -= sb.x; ry -= sb.y;
        }
        if (subF) {
            float2 sb = __ldg((const float2*)subF + (size_t)gw * (STRIDE / 2) + lane);
            rx -= sb.x; ry -= sb.y;
        }
        size_t off = (size_t)gw * HSTRIDE + lane;
        if (dstR) dstR[off] = __floats2half2_rn(rx, ry);
        dstS[off] = __floats2half2_rn(di * rx, di * ry);
    }
}

// ---------------- last prop fused with head ----------------
__global__ void __launch_bounds__(256) prop_head(const __half2* __restrict__ src,
                                                 const float* __restrict__ P,
                                                 const __half2* __restrict__ subH,
                                                 const float* __restrict__ cheb_b,
                                                 const float* __restrict__ fc_w,
                                                 const float* __restrict__ fc_b,
                                                 float* __restrict__ out) {
    __shared__ __align__(8) float s_fcwT[D_OUT * 52];
    __shared__ float s_b[D_HID];
    __shared__ float s_fcb[D_OUT];
    int tid = threadIdx.x;
    for (int i = tid; i < D_HID * D_OUT; i += blockDim.x) {
        int j = i / D_OUT, o = i % D_OUT;
        s_fcwT[o * 52 + j] = fc_w[i];
    }
    if (tid < D_OUT) { s_fcwT[tid * 52 + 50] = 0.f; s_fcwT[tid * 52 + 51] = 0.f; }
    if (tid < D_HID) s_b[tid] = cheb_b[tid];
    if (tid < D_OUT) s_fcb[tid] = fc_b[tid];
    __syncthreads();

    int gw = (blockIdx.x * blockDim.x + tid) >> 5;
    int lane = tid & 31;
    if (gw >= N_NODES) return;
    int deg = __ldg(&g_cursor[gw]);
    if (deg > CAP) deg = CAP;
    const unsigned short* row = g_bucket + (size_t)gw * CAP;
    const bool act = lane < 25;
    float Sx, Sy;
    row_sum_h(src, row, deg, act, lane, Sx, Sy);

    float l[D_OUT];
    if (act) {
        float di = __ldg(&g_dinv[gw]);
        float2 p  = __ldg((const float2*)P + (size_t)gw * (STRIDE / 2) + lane);
        float2 sb = __half22float2(__ldg(subH + (size_t)gw * HSTRIDE + lane));
        float hx = fmaxf(p.x - di * Sx - sb.x + s_b[2 * lane],     0.0f);  // scale = 1
        float hy = fmaxf(p.y - di * Sy - sb.y + s_b[2 * lane + 1], 0.0f);
        #pragma unroll
        for (int o = 0; o < D_OUT; o++) {
            float2 w2 = ((const float2*)(s_fcwT + o * 52))[lane];
            l[o] = hx * w2.x + hy * w2.y;
        }
    } else {
        #pragma unroll
        for (int o = 0; o < D_OUT; o++) l[o] = 0.0f;
    }

    #pragma unroll
    for (int offm = 16; offm > 0; offm >>= 1) {
        #pragma unroll
        for (int o = 0; o < D_OUT; o++)
            l[o] += __shfl_xor_sync(0xffffffffu, l[o], offm);
    }

    if (lane == 0) {
        #pragma unroll
        for (int o = 0; o < D_OUT; o++) l[o] += s_fcb[o];
        float m = l[0];
        #pragma unroll
        for (int o = 1; o < D_OUT; o++) m = fmaxf(m, l[o]);
        float ssum = 0.0f;
        #pragma unroll
        for (int o = 0; o < D_OUT; o++) ssum += expf(l[o] - m);
        float lse = m + logf(ssum);
        float* orow = out + (size_t)gw * D_OUT;
        #pragma unroll
        for (int o = 0; o < D_OUT; o++) orow[o] = l[o] - lse;
    }
}

// ---------------- launch ----------------
extern "C" void kernel_launch(void* const* d_in, const int* in_sizes, int n_in,
                              void* d_out, int out_size) {
    const float* x      = (const float*)d_in[0];
    const void*  ei     = d_in[1];
    const float* cheb_w = (const float*)d_in[2];
    const float* cheb_b = (const float*)d_in[3];
    const float* fc_w   = (const float*)d_in[4];
    const float* fc_b   = (const float*)d_in[5];
    float* out = (float*)d_out;

    float *P, *Pb;
    __half2 *P4s, *b3s, *b3r, *b2s, *b2r, *b1s;
    cudaGetSymbolAddress((void**)&P,   g_P);
    cudaGetSymbolAddress((void**)&Pb,  g_Pb);
    cudaGetSymbolAddress((void**)&P4s, g_P4s);
    cudaGetSymbolAddress((void**)&b3s, g_b3s);
    cudaGetSymbolAddress((void**)&b3r, g_b3r);
    cudaGetSymbolAddress((void**)&b2s, g_b2s);
    cudaGetSymbolAddress((void**)&b2r, g_b2r);
    cudaGetSymbolAddress((void**)&b1s, g_b1s);
    const size_t PS = (size_t)N_NODES * STRIDE;
    float* P0  = P  + 0 * PS;
    float* P1  = P  + 1 * PS;
    float* P2  = P  + 2 * PS;
    float* P3  = P  + 3 * PS;
    float* P4  = P  + 4 * PS;
    float* P3b = Pb + 0 * PS;
    float* P4b = Pb + 1 * PS;

    const int TB = 256;
    const int NODE_BLK = (N_NODES + TB - 1) / TB;
    const int HALF_EDGE_BLK = (N_EDGES / 2 + TB - 1) / TB;
    const long long PT = (long long)N_NODES * 32;
    const int PROP_BLK = (int)((PT + TB - 1) / TB);
    const int PROJ_GX = (N_NODES + 255) / 256;   // 196 blocks, 2 nodes/thread

    static cudaStream_t s_proj = nullptr;
    static cudaEvent_t evA = nullptr, ev2 = nullptr, ev1 = nullptr, ev0 = nullptr, ev_fork = nullptr;
    static int use_async = -1;
    if (use_async < 0) {
        bool ok = (cudaStreamCreateWithFlags(&s_proj, cudaStreamNonBlocking) == cudaSuccess);
        ok = ok && (cudaEventCreateWithFlags(&ev_fork, cudaEventDisableTiming) == cudaSuccess);
        ok = ok && (cudaEventCreateWithFlags(&evA, cudaEventDisableTiming) == cudaSuccess);
        ok = ok && (cudaEventCreateWithFlags(&ev2, cudaEventDisableTiming) == cudaSuccess);
        ok = ok && (cudaEventCreateWithFlags(&ev1, cudaEventDisableTiming) == cudaSuccess);
        ok = ok && (cudaEventCreateWithFlags(&ev0, cudaEventDisableTiming) == cudaSuccess);
        use_async = ok ? 1 : 0;
    }

    if (use_async) {
        // ---- fork: critical projections k=3,4 as 4 independent half-K partials ----
        cudaEventRecord(ev_fork, 0);
        cudaStreamWaitEvent(s_proj, ev_fork, 0);
        proj_half_kernel<<<PROJ_GX, 128, 0, s_proj>>>(x, cheb_w, 4, 0, P4);
        proj_half_kernel<<<PROJ_GX, 128, 0, s_proj>>>(x, cheb_w, 4, 1, P4b);
        proj_half_kernel<<<PROJ_GX, 128, 0, s_proj>>>(x, cheb_w, 3, 0, P3);
        proj_half_kernel<<<PROJ_GX, 128, 0, s_proj>>>(x, cheb_w, 3, 1, P3b);
        cudaEventRecord(evA, s_proj);
        proj_kernel<<<dim3(PROJ_GX, 1), 128, 0, s_proj>>>(x, cheb_w, 2);  // k=2
        cudaEventRecord(ev2, s_proj);
        proj_kernel<<<dim3(PROJ_GX, 1), 128, 0, s_proj>>>(x, cheb_w, 1);  // k=1
        cudaEventRecord(ev1, s_proj);
        proj_kernel<<<dim3(PROJ_GX, 1), 128, 0, s_proj>>>(x, cheb_w, 0);  // k=0
        cudaEventRecord(ev0, s_proj);

        // ---- single-pass bucket CSR (main stream, concurrent) ----
        init_kernel<<<NODE_BLK, TB>>>((const int*)ei);
        scatter_kernel<<<HALF_EDGE_BLK, TB>>>(ei);
        dinv_kernel<<<NODE_BLK, TB>>>();

        // ---- Clenshaw ----
        cudaStreamWaitEvent(0, evA, 0);
        scaleP4_kernel<<<PROP_BLK, TB>>>();   // P4 = P4a+P4b (fp32), P4s = D*P4 (fp16)
        prop_b<<<PROP_BLK, TB>>>(P4s, P3, P3b, nullptr, nullptr, 2.0f, b3r, b3s); // b3 = P3 + 2L P4
        cudaStreamWaitEvent(0, ev2, 0);
        prop_b<<<PROP_BLK, TB>>>(b3s, P2, nullptr, nullptr, P4, 2.0f, b2r, b2s);  // b2 = P2 + 2L b3 - P4
        cudaStreamWaitEvent(0, ev1, 0);
        prop_b<<<PROP_BLK, TB>>>(b2s, P1, nullptr, b3r, nullptr, 2.0f, nullptr, b1s); // b1 = P1 + 2L b2 - b3
        cudaStreamWaitEvent(0, ev0, 0);
        prop_head<<<PROP_BLK, TB>>>(b1s, P0, b2r, cheb_b, fc_w, fc_b, out);
    } else {
        // serial fallback
        init_kernel<<<NODE_BLK, TB>>>((const int*)ei);
        scatter_kernel<<<HALF_EDGE_BLK, TB>>>(ei);
        dinv_kernel<<<NODE_BLK, TB>>>();
        proj_half_kernel<<<PROJ_GX, 128>>>(x, cheb_w, 4, 0, P4);
        proj_half_kernel<<<PROJ_GX, 128>>>(x, cheb_w, 4, 1, P4b);
        proj_half_kernel<<<PROJ_GX, 128>>>(x, cheb_w, 3, 0, P3);
        proj_half_kernel<<<PROJ_GX, 128>>>(x, cheb_w, 3, 1, P3b);
        proj_kernel<<<dim3(PROJ_GX, 3), 128>>>(x, cheb_w, 0);  // k=0,1,2
        scaleP4_kernel<<<PROP_BLK, TB>>>();
        prop_b<<<PROP_BLK, TB>>>(P4s, P3, P3b, nullptr, nullptr, 2.0f, b3r, b3s);
        prop_b<<<PROP_BLK, TB>>>(b3s, P2, nullptr, nullptr, P4, 2.0f, b2r, b2s);
        prop_b<<<PROP_BLK, TB>>>(b2s, P1, nullptr, b3r, nullptr, 2.0f, nullptr, b1s);
        prop_head<<<PROP_BLK, TB>>>(b1s, P0, b2r, cheb_b, fc_w, fc_b, out);
    }
}

// round 14
// speedup vs baseline: 1.0772x; 1.0772x over previous
#include <cuda_runtime.h>
#include <cuda_fp16.h>
#include <math.h>

#define N_NODES 50000
#define N_EDGES 1600000
#define D_IN    128
#define D_HID   50
#define D_OUT   10
#define STRIDE  64   // fp32 row stride (floats) for P buffers
#define HSTRIDE 32   // fp16 row stride (half2 units) = 128 bytes
#define CAP     128  // bucket capacity per row (17-sigma headroom over mean 32)

// ---------------- static scratch ----------------
__device__ float g_Pa[(size_t)5 * N_NODES * STRIDE];              // K-half-A partials
__device__ float g_Pb[(size_t)5 * N_NODES * STRIDE];              // K-half-B partials
__device__ __align__(128) __half2 g_P4s[(size_t)N_NODES * HSTRIDE];  // D*P4
__device__ __align__(128) __half2 g_b3s[(size_t)N_NODES * HSTRIDE];  // D*b3
__device__ __align__(128) __half2 g_b3r[(size_t)N_NODES * HSTRIDE];  // b3 real
__device__ __align__(128) __half2 g_b2s[(size_t)N_NODES * HSTRIDE];
__device__ __align__(128) __half2 g_b2r[(size_t)N_NODES * HSTRIDE];
__device__ __align__(128) __half2 g_b1s[(size_t)N_NODES * HSTRIDE];
__device__ int   g_cursor[N_NODES];                                // degree counters
__device__ float g_dinv  [N_NODES];
__device__ __align__(16) unsigned short g_bucket[(size_t)N_NODES * CAP];
__device__ int   g_is64;

// ---------------- init: zero cursors + dtype detect ----------------
__global__ void init_kernel(const int* __restrict__ ei32) {
    int i = blockIdx.x * blockDim.x + threadIdx.x;
    if (i < N_NODES) g_cursor[i] = 0;
    if (blockIdx.x == 0) {
        __shared__ int nz;
        if (threadIdx.x == 0) nz = 0;
        __syncthreads();
        // int64 edge_index with values<50000 has all-zero high words
        if (ei32[2 * threadIdx.x + 1] != 0) atomicExch(&nz, 1);
        __syncthreads();
        if (threadIdx.x == 0) g_is64 = (nz == 0) ? 1 : 0;
    }
}

// ---------------- scatter: single-pass bucket CSR (cols only), 2 edges/thread ----
__global__ void scatter_kernel(const void* __restrict__ ei) {
    int t = blockIdx.x * blockDim.x + threadIdx.x;
    if (t >= N_EDGES / 2) return;
    int r0, r1, c0, c1;
    if (g_is64) {
        longlong2 rv = __ldg((const longlong2*)ei + t);
        longlong2 cv = __ldg((const longlong2*)ei + (N_EDGES / 2) + t);
        r0 = (int)rv.x; r1 = (int)rv.y; c0 = (int)cv.x; c1 = (int)cv.y;
    } else {
        int2 rv = __ldg((const int2*)ei + t);
        int2 cv = __ldg((const int2*)ei + (N_EDGES / 2) + t);
        r0 = rv.x; r1 = rv.y; c0 = cv.x; c1 = cv.y;
    }
    int p0 = atomicAdd(&g_cursor[r0], 1);
    if (p0 < CAP) g_bucket[(size_t)r0 * CAP + p0] = (unsigned short)c0;
    int p1 = atomicAdd(&g_cursor[r1], 1);
    if (p1 < CAP) g_bucket[(size_t)r1 * CAP + p1] = (unsigned short)c1;
}

// ---------------- dinv from the post-scatter cursors ----------------
__global__ void dinv_kernel() {
    int n = blockIdx.x * blockDim.x + threadIdx.x;
    if (n >= N_NODES) return;
    int d = g_cursor[n];
    g_dinv[n] = (d > 0) ? rsqrtf((float)d) : 0.0f;
}

// ------- combine P4 halves -> fp32 P4 (into g_Pa[4]) + fp16 D*P4, warp per row ---
__global__ void __launch_bounds__(256) scaleP4_kernel() {
    int gw = (blockIdx.x * blockDim.x + threadIdx.x) >> 5;
    int lane = threadIdx.x & 31;
    if (gw >= N_NODES || lane >= 25) return;
    float di = __ldg(&g_dinv[gw]);
    float2* p4a = (float2*)(g_Pa + ((size_t)4 * N_NODES + gw) * STRIDE) + lane;
    const float2* p4b = (const float2*)(g_Pb + ((size_t)4 * N_NODES + gw) * STRIDE) + lane;
    float2 a = __ldg((const float2*)p4a);
    float2 b = __ldg(p4b);
    float sx = a.x + b.x, sy = a.y + b.y;
    *p4a = make_float2(sx, sy);                      // combined fp32 for prop2's sub
    g_P4s[(size_t)gw * HSTRIDE + lane] = __floats2half2_rn(di * sx, di * sy);
}

// ---------------- f32x2 helpers ----------------
__device__ __forceinline__ unsigned long long pack2(float lo, float hi) {
    unsigned long long r;
    asm("mov.b64 %0, {%1, %2};" : "=l"(r) : "f"(lo), "f"(hi));
    return r;
}
__device__ __forceinline__ void unpack2(unsigned long long v, float& lo, float& hi) {
    asm("mov.b64 {%0, %1}, %2;" : "=f"(lo), "=f"(hi) : "l"(v));
}
#define FMA2(acc, a, b) asm("fma.rn.f32x2 %0, %1, %2, %0;" : "+l"(acc) : "l"(a), "l"(b))

// ---------------- half-K partial projection, y-packed ----------------------------
// blockIdx.y selects (k, half): k = k_base + y/2, half = y%2.
// Computes x[:, 64h:64h+64] @ W_k[64h:64h+64, :] into g_Pa/g_Pb[k].
__global__ void __launch_bounds__(128) proj_half_kernel(const float* __restrict__ x,
                                                        const float* __restrict__ cheb_w,
                                                        int k_base) {
    __shared__ __align__(16) float Wsm[64 * 52];
    int tid = threadIdx.x;
    int k = k_base + (blockIdx.y >> 1);
    int half = blockIdx.y & 1;
    const float* W = cheb_w + ((size_t)k * D_IN + half * 64) * D_HID;
    if (tid < 64) {
        #pragma unroll 1
        for (int o = 0; o < D_HID; o++) Wsm[tid * 52 + o] = W[tid * D_HID + o];
        Wsm[tid * 52 + 50] = 0.0f;
        Wsm[tid * 52 + 51] = 0.0f;
    }
    __syncthreads();

    int n0 = blockIdx.x * 256 + tid;
    int n1 = n0 + 128;
    bool v0 = n0 < N_NODES;
    bool v1 = n1 < N_NODES;

    unsigned long long acc0[26], acc1[26];
    #pragma unroll
    for (int p = 0; p < 26; p++) { acc0[p] = 0ull; acc1[p] = 0ull; }

    const float4* A0 = (const float4*)(x + (size_t)n0 * D_IN + half * 64);
    const float4* A1 = (const float4*)(x + (size_t)n1 * D_IN + half * 64);
    float4 z4 = make_float4(0.f, 0.f, 0.f, 0.f);
    float4 a0 = v0 ? __ldg(A0) : z4;
    float4 a1 = v1 ? __ldg(A1) : z4;

    #pragma unroll 1
    for (int ic = 0; ic < 16; ic++) {
        float4 a0n = z4, a1n = z4;
        if (ic < 15) {
            if (v0) a0n = __ldg(A0 + ic + 1);
            if (v1) a1n = __ldg(A1 + ic + 1);
        }
        float av0[4] = {a0.x, a0.y, a0.z, a0.w};
        float av1[4] = {a1.x, a1.y, a1.z, a1.w};
        #pragma unroll
        for (int j = 0; j < 4; j++) {
            unsigned long long a0p = pack2(av0[j], av0[j]);
            unsigned long long a1p = pack2(av1[j], av1[j]);
            const float4* wrow = (const float4*)(Wsm + (ic * 4 + j) * 52);
            #pragma unroll
            for (int q = 0; q < 13; q++) {
                float4 wv = wrow[q];
                unsigned long long w01 = pack2(wv.x, wv.y);
                unsigned long long w23 = pack2(wv.z, wv.w);
                FMA2(acc0[2 * q],     w01, a0p);
                FMA2(acc0[2 * q + 1], w23, a0p);
                FMA2(acc1[2 * q],     w01, a1p);
                FMA2(acc1[2 * q + 1], w23, a1p);
            }
        }
        a0 = a0n; a1 = a1n;
    }

    float* base = (half ? g_Pb : g_Pa) + (size_t)k * N_NODES * STRIDE;
    #pragma unroll
    for (int which = 0; which < 2; which++) {
        bool v = which ? v1 : v0;
        int n = which ? n1 : n0;
        unsigned long long* acc = which ? acc1 : acc0;
        if (!v) continue;
        float* dst = base + (size_t)n * STRIDE;
        #pragma unroll
        for (int q = 0; q < 12; q++) {
            float x0, x1, x2, x3;
            unpack2(acc[2 * q], x0, x1);
            unpack2(acc[2 * q + 1], x2, x3);
            ((float4*)dst)[q] = make_float4(x0, x1, x2, x3);
        }
        float x0, x1; unpack2(acc[24], x0, x1);
        ((float2*)dst)[24] = make_float2(x0, x1);
    }
}

// ---------------- weightless gather accumulate: uint16 bucket, aligned bursts -----
__device__ __forceinline__ void row_sum_h(const __half2* __restrict__ src,
                                          const unsigned short* __restrict__ row,
                                          int deg, bool act, int lane,
                                          float& Sx, float& Sy) {
    float ax0 = 0.f, ay0 = 0.f, ax1 = 0.f, ay1 = 0.f;
    int i = 0;
    #pragma unroll 1
    for (; i + 8 <= deg; i += 8) {
        uint4 cp = __ldg((const uint4*)(row + i));       // 8 cols, 16B aligned
        unsigned c[8];
        c[0] = cp.x & 0xffffu; c[1] = cp.x >> 16;
        c[2] = cp.y & 0xffffu; c[3] = cp.y >> 16;
        c[4] = cp.z & 0xffffu; c[5] = cp.z >> 16;
        c[6] = cp.w & 0xffffu; c[7] = cp.w >> 16;
        if (act) {
            __half2 v[8];
            #pragma unroll
            for (int u = 0; u < 8; u++)
                v[u] = __ldcg((__half2*)(src + (size_t)c[u] * HSTRIDE + lane));
            #pragma unroll
            for (int u = 0; u < 8; u++) {
                float2 vf = __half22float2(v[u]);
                if (u & 1) { ax1 += vf.x; ay1 += vf.y; }
                else       { ax0 += vf.x; ay0 += vf.y; }
            }
        }
    }
    if (deg - i >= 4) {
        uint2 cp = __ldg((const uint2*)(row + i));       // 8B aligned
        unsigned c[4];
        c[0] = cp.x & 0xffffu; c[1] = cp.x >> 16;
        c[2] = cp.y & 0xffffu; c[3] = cp.y >> 16;
        if (act) {
            #pragma unroll
            for (int u = 0; u < 4; u++) {
                float2 vf = __half22float2(
                    __ldcg((__half2*)(src + (size_t)c[u] * HSTRIDE + lane)));
                if (u & 1) { ax1 += vf.x; ay1 += vf.y; }
                else       { ax0 += vf.x; ay0 += vf.y; }
            }
        }
        i += 4;
    }
    if (deg - i >= 2) {
        unsigned cp = __ldg((const unsigned*)(row + i)); // 4B aligned
        unsigned c0 = cp & 0xffffu, c1 = cp >> 16;
        if (act) {
            float2 v0 = __half22float2(__ldcg((__half2*)(src + (size_t)c0 * HSTRIDE + lane)));
            float2 v1 = __half22float2(__ldcg((__half2*)(src + (size_t)c1 * HSTRIDE + lane)));
            ax0 += v0.x; ay0 += v0.y;
            ax1 += v1.x; ay1 += v1.y;
        }
        i += 2;
    }
    if (i < deg) {
        unsigned c = __ldg(row + i);
        if (act) {
            float2 v = __half22float2(__ldcg((__half2*)(src + (size_t)c * HSTRIDE + lane)));
            ax0 += v.x; ay0 += v.y;
        }
    }
    Sx = ax0 + ax1;
    Sy = ay0 + ay1;
}

// ------- Clenshaw prop: real = P (+Padd) - scale*dinv*S - sub; scaled = dinv*real
__global__ void __launch_bounds__(256) prop_b(const __half2* __restrict__ src,
                                              const float* __restrict__ P,
                                              const float* __restrict__ Padd,
                                              const __half2* __restrict__ subH,
                                              const float* __restrict__ subF,
                                              float scale,
                                              __half2* __restrict__ dstR,
                                              __half2* __restrict__ dstS) {
    int gw = (blockIdx.x * blockDim.x + threadIdx.x) >> 5;
    int lane = threadIdx.x & 31;
    if (gw >= N_NODES) return;
    int deg = __ldg(&g_cursor[gw]);
    if (deg > CAP) deg = CAP;
    const unsigned short* row = g_bucket + (size_t)gw * CAP;
    const bool act = lane < 25;
    float Sx, Sy;
    row_sum_h(src, row, deg, act, lane, Sx, Sy);

    if (act) {
        float di = __ldg(&g_dinv[gw]);
        float2 p = __ldg((const float2*)P + (size_t)gw * (STRIDE / 2) + lane);
        float sdi = scale * di;
        float rx = p.x - sdi * Sx;
        float ry = p.y - sdi * Sy;
        if (Padd) {
            float2 pa = __ldg((const float2*)Padd + (size_t)gw * (STRIDE / 2) + lane);
            rx += pa.x; ry += pa.y;
        }
        if (subH) {
            float2 sb = __half22float2(__ldg(subH + (size_t)gw * HSTRIDE + lane));
            rx -= sb.x; ry -= sb.y;
        }
        if (subF) {
            float2 sb = __ldg((const float2*)subF + (size_t)gw * (STRIDE / 2) + lane);
            rx -= sb.x; ry -= sb.y;
        }
        size_t off = (size_t)gw * HSTRIDE + lane;
        if (dstR) dstR[off] = __floats2half2_rn(rx, ry);
        dstS[off] = __floats2half2_rn(di * rx, di * ry);
    }
}

// ---------------- last prop fused with head ----------------
__global__ void __launch_bounds__(256) prop_head(const __half2* __restrict__ src,
                                                 const float* __restrict__ P,
                                                 const float* __restrict__ Padd,
                                                 const __half2* __restrict__ subH,
                                                 const float* __restrict__ cheb_b,
                                                 const float* __restrict__ fc_w,
                                                 const float* __restrict__ fc_b,
                                                 float* __restrict__ out) {
    __shared__ __align__(8) float s_fcwT[D_OUT * 52];
    __shared__ float s_b[D_HID];
    __shared__ float s_fcb[D_OUT];
    int tid = threadIdx.x;
    for (int i = tid; i < D_HID * D_OUT; i += blockDim.x) {
        int j = i / D_OUT, o = i % D_OUT;
        s_fcwT[o * 52 + j] = fc_w[i];
    }
    if (tid < D_OUT) { s_fcwT[tid * 52 + 50] = 0.f; s_fcwT[tid * 52 + 51] = 0.f; }
    if (tid < D_HID) s_b[tid] = cheb_b[tid];
    if (tid < D_OUT) s_fcb[tid] = fc_b[tid];
    __syncthreads();

    int gw = (blockIdx.x * blockDim.x + tid) >> 5;
    int lane = tid & 31;
    if (gw >= N_NODES) return;
    int deg = __ldg(&g_cursor[gw]);
    if (deg > CAP) deg = CAP;
    const unsigned short* row = g_bucket + (size_t)gw * CAP;
    const bool act = lane < 25;
    float Sx, Sy;
    row_sum_h(src, row, deg, act, lane, Sx, Sy);

    float l[D_OUT];
    if (act) {
        float di = __ldg(&g_dinv[gw]);
        float2 p  = __ldg((const float2*)P + (size_t)gw * (STRIDE / 2) + lane);
        float2 pa = __ldg((const float2*)Padd + (size_t)gw * (STRIDE / 2) + lane);
        float2 sb = __half22float2(__ldg(subH + (size_t)gw * HSTRIDE + lane));
        float hx = fmaxf(p.x + pa.x - di * Sx - sb.x + s_b[2 * lane],     0.0f);  // scale = 1
        float hy = fmaxf(p.y + pa.y - di * Sy - sb.y + s_b[2 * lane + 1], 0.0f);
        #pragma unroll
        for (int o = 0; o < D_OUT; o++) {
            float2 w2 = ((const float2*)(s_fcwT + o * 52))[lane];
            l[o] = hx * w2.x + hy * w2.y;
        }
    } else {
        #pragma unroll
        for (int o = 0; o < D_OUT; o++) l[o] = 0.0f;
    }

    #pragma unroll
    for (int offm = 16; offm > 0; offm >>= 1) {
        #pragma unroll
        for (int o = 0; o < D_OUT; o++)
            l[o] += __shfl_xor_sync(0xffffffffu, l[o], offm);
    }

    if (lane == 0) {
        #pragma unroll
        for (int o = 0; o < D_OUT; o++) l[o] += s_fcb[o];
        float m = l[0];
        #pragma unroll
        for (int o = 1; o < D_OUT; o++) m = fmaxf(m, l[o]);
        float ssum = 0.0f;
        #pragma unroll
        for (int o = 0; o < D_OUT; o++) ssum += expf(l[o] - m);
        float lse = m + logf(ssum);
        float* orow = out + (size_t)gw * D_OUT;
        #pragma unroll
        for (int o = 0; o < D_OUT; o++) orow[o] = l[o] - lse;
    }
}

// ---------------- launch ----------------
extern "C" void kernel_launch(void* const* d_in, const int* in_sizes, int n_in,
                              void* d_out, int out_size) {
    const float* x      = (const float*)d_in[0];
    const void*  ei     = d_in[1];
    const float* cheb_w = (const float*)d_in[2];
    const float* cheb_b = (const float*)d_in[3];
    const float* fc_w   = (const float*)d_in[4];
    const float* fc_b   = (const float*)d_in[5];
    float* out = (float*)d_out;

    float *Pa, *Pb;
    __half2 *P4s, *b3s, *b3r, *b2s, *b2r, *b1s;
    cudaGetSymbolAddress((void**)&Pa,  g_Pa);
    cudaGetSymbolAddress((void**)&Pb,  g_Pb);
    cudaGetSymbolAddress((void**)&P4s, g_P4s);
    cudaGetSymbolAddress((void**)&b3s, g_b3s);
    cudaGetSymbolAddress((void**)&b3r, g_b3r);
    cudaGetSymbolAddress((void**)&b2s, g_b2s);
    cudaGetSymbolAddress((void**)&b2r, g_b2r);
    cudaGetSymbolAddress((void**)&b1s, g_b1s);
    const size_t PS = (size_t)N_NODES * STRIDE;
    float* P0a = Pa + 0 * PS;  float* P0b = Pb + 0 * PS;
    float* P1a = Pa + 1 * PS;  float* P1b = Pb + 1 * PS;
    float* P2a = Pa + 2 * PS;  float* P2b = Pb + 2 * PS;
    float* P3a = Pa + 3 * PS;  float* P3b = Pb + 3 * PS;
    float* P4a = Pa + 4 * PS;  // P4 combined in-place by scaleP4

    const int TB = 256;
    const int NODE_BLK = (N_NODES + TB - 1) / TB;
    const int HALF_EDGE_BLK = (N_EDGES / 2 + TB - 1) / TB;
    const long long PT = (long long)N_NODES * 32;
    const int PROP_BLK = (int)((PT + TB - 1) / TB);
    const int PROJ_GX = (N_NODES + 255) / 256;   // 196 blocks, 2 nodes/thread

    static cudaStream_t s_proj = nullptr;
    static cudaEvent_t ev_fork = nullptr, evA = nullptr, evB = nullptr;
    static int use_async = -1;
    if (use_async < 0) {
        bool ok = (cudaStreamCreateWithFlags(&s_proj, cudaStreamNonBlocking) == cudaSuccess);
        ok = ok && (cudaEventCreateWithFlags(&ev_fork, cudaEventDisableTiming) == cudaSuccess);
        ok = ok && (cudaEventCreateWithFlags(&evA, cudaEventDisableTiming) == cudaSuccess);
        ok = ok && (cudaEventCreateWithFlags(&evB, cudaEventDisableTiming) == cudaSuccess);
        use_async = ok ? 1 : 0;
    }

    if (use_async) {
        // ---- fork: y-packed half-K projections on ONE side stream ----
        cudaEventRecord(ev_fork, 0);
        cudaStreamWaitEvent(s_proj, ev_fork, 0);
        proj_half_kernel<<<dim3(PROJ_GX, 4), 128, 0, s_proj>>>(x, cheb_w, 3); // k=3,4 halves
        cudaEventRecord(evA, s_proj);
        proj_half_kernel<<<dim3(PROJ_GX, 6), 128, 0, s_proj>>>(x, cheb_w, 0); // k=0,1,2 halves
        cudaEventRecord(evB, s_proj);

        // ---- single-pass bucket CSR (main stream, concurrent) ----
        init_kernel<<<NODE_BLK, TB>>>((const int*)ei);
        scatter_kernel<<<HALF_EDGE_BLK, TB>>>(ei);
        dinv_kernel<<<NODE_BLK, TB>>>();

        // ---- Clenshaw ----
        cudaStreamWaitEvent(0, evA, 0);
        scaleP4_kernel<<<PROP_BLK, TB>>>();   // P4a += P4b (fp32), P4s = D*P4 (fp16)
        prop_b<<<PROP_BLK, TB>>>(P4s, P3a, P3b, nullptr, nullptr, 2.0f, b3r, b3s); // b3 = P3 + 2L P4
        cudaStreamWaitEvent(0, evB, 0);
        prop_b<<<PROP_BLK, TB>>>(b3s, P2a, P2b, nullptr, P4a, 2.0f, b2r, b2s);     // b2 = P2 + 2L b3 - P4
        prop_b<<<PROP_BLK, TB>>>(b2s, P1a, P1b, b3r, nullptr, 2.0f, nullptr, b1s); // b1 = P1 + 2L b2 - b3
        prop_head<<<PROP_BLK, TB>>>(b1s, P0a, P0b, b2r, cheb_b, fc_w, fc_b, out);
    } else {
        // serial fallback
        init_kernel<<<NODE_BLK, TB>>>((const int*)ei);
        scatter_kernel<<<HALF_EDGE_BLK, TB>>>(ei);
        dinv_kernel<<<NODE_BLK, TB>>>();
        proj_half_kernel<<<dim3(PROJ_GX, 4), 128>>>(x, cheb_w, 3);
        proj_half_kernel<<<dim3(PROJ_GX, 6), 128>>>(x, cheb_w, 0);
        scaleP4_kernel<<<PROP_BLK, TB>>>();
        prop_b<<<PROP_BLK, TB>>>(P4s, P3a, P3b, nullptr, nullptr, 2.0f, b3r, b3s);
        prop_b<<<PROP_BLK, TB>>>(b3s, P2a, P2b, nullptr, P4a, 2.0f, b2r, b2s);
        prop_b<<<PROP_BLK, TB>>>(b2s, P1a, P1b, b3r, nullptr, 2.0f, nullptr, b1s);
        prop_head<<<PROP_BLK, TB>>>(b1s, P0a, P0b, b2r, cheb_b, fc_w, fc_b, out);
    }
}

// round 15
// speedup vs baseline: 1.1726x; 1.0886x over previous
#include <cuda_runtime.h>
#include <cuda_fp16.h>
#include <math.h>

#define N_NODES 50000
#define N_EDGES 1600000
#define D_IN    128
#define D_HID   50
#define D_OUT   10
#define STRIDE  64   // fp32 row stride (floats) for P0..P4
#define HSTRIDE 32   // fp16 row stride (half2 units) = 128 bytes
#define CAP     128  // bucket capacity per row (17-sigma headroom over mean 32)

// ---------------- static scratch ----------------
__device__ float g_P [(size_t)5 * N_NODES * STRIDE];              // P0..P4 fp32
__device__ float g_Pb[(size_t)2 * N_NODES * STRIDE];              // K-half-B partials: [0]=P3b, [1]=P4b
__device__ __align__(128) __half2 g_P4s[(size_t)N_NODES * HSTRIDE];  // D*P4
__device__ __align__(128) __half2 g_b3s[(size_t)N_NODES * HSTRIDE];  // D*b3
__device__ __align__(128) __half2 g_b3r[(size_t)N_NODES * HSTRIDE];  // b3 real
__device__ __align__(128) __half2 g_b2s[(size_t)N_NODES * HSTRIDE];
__device__ __align__(128) __half2 g_b2r[(size_t)N_NODES * HSTRIDE];
__device__ __align__(128) __half2 g_b1s[(size_t)N_NODES * HSTRIDE];
__device__ int   g_cursor[N_NODES];                                // degree counters
__device__ float g_dinv  [N_NODES];
__device__ __align__(16) unsigned short g_bucket[(size_t)N_NODES * CAP];
__device__ int   g_is64;

// ---------------- init: zero cursors + dtype detect ----------------
__global__ void init_kernel(const int* __restrict__ ei32) {
    int i = blockIdx.x * blockDim.x + threadIdx.x;
    if (i < N_NODES) g_cursor[i] = 0;
    if (blockIdx.x == 0) {
        __shared__ int nz;
        if (threadIdx.x == 0) nz = 0;
        __syncthreads();
        // int64 edge_index with values<50000 has all-zero high words
        if (ei32[2 * threadIdx.x + 1] != 0) atomicExch(&nz, 1);
        __syncthreads();
        if (threadIdx.x == 0) g_is64 = (nz == 0) ? 1 : 0;
    }
}

// ---------------- scatter: single-pass bucket CSR (cols only), 2 edges/thread ----
__global__ void scatter_kernel(const void* __restrict__ ei) {
    int t = blockIdx.x * blockDim.x + threadIdx.x;
    if (t >= N_EDGES / 2) return;
    int r0, r1, c0, c1;
    if (g_is64) {
        longlong2 rv = __ldg((const longlong2*)ei + t);
        longlong2 cv = __ldg((const longlong2*)ei + (N_EDGES / 2) + t);
        r0 = (int)rv.x; r1 = (int)rv.y; c0 = (int)cv.x; c1 = (int)cv.y;
    } else {
        int2 rv = __ldg((const int2*)ei + t);
        int2 cv = __ldg((const int2*)ei + (N_EDGES / 2) + t);
        r0 = rv.x; r1 = rv.y; c0 = cv.x; c1 = cv.y;
    }
    int p0 = atomicAdd(&g_cursor[r0], 1);
    if (p0 < CAP) g_bucket[(size_t)r0 * CAP + p0] = (unsigned short)c0;
    int p1 = atomicAdd(&g_cursor[r1], 1);
    if (p1 < CAP) g_bucket[(size_t)r1 * CAP + p1] = (unsigned short)c1;
}

// ---------------- dinv from the post-scatter cursors ----------------
__global__ void dinv_kernel() {
    int n = blockIdx.x * blockDim.x + threadIdx.x;
    if (n >= N_NODES) return;
    int d = g_cursor[n];
    g_dinv[n] = (d > 0) ? rsqrtf((float)d) : 0.0f;
}

// ------- combine P4 halves -> fp32 P4 (in place) + fp16 D*P4, warp per row -------
__global__ void __launch_bounds__(256) scaleP4_kernel() {
    int gw = (blockIdx.x * blockDim.x + threadIdx.x) >> 5;
    int lane = threadIdx.x & 31;
    if (gw >= N_NODES || lane >= 25) return;
    float di = __ldg(&g_dinv[gw]);
    float2* p4 = (float2*)(g_P + ((size_t)4 * N_NODES + gw) * STRIDE) + lane;
    const float2* p4b = (const float2*)(g_Pb + ((size_t)1 * N_NODES + gw) * STRIDE) + lane;
    float2 a = __ldg((const float2*)p4);
    float2 b = __ldg(p4b);
    float sx = a.x + b.x, sy = a.y + b.y;
    *p4 = make_float2(sx, sy);                       // combined fp32 for prop2's sub
    g_P4s[(size_t)gw * HSTRIDE + lane] = __floats2half2_rn(di * sx, di * sy);
}

// ---------------- f32x2 helpers ----------------
__device__ __forceinline__ unsigned long long pack2(float lo, float hi) {
    unsigned long long r;
    asm("mov.b64 %0, {%1, %2};" : "=l"(r) : "f"(lo), "f"(hi));
    return r;
}
__device__ __forceinline__ void unpack2(unsigned long long v, float& lo, float& hi) {
    asm("mov.b64 {%0, %1}, %2;" : "=f"(lo), "=f"(hi) : "l"(v));
}
#define FMA2(acc, a, b) asm("fma.rn.f32x2 %0, %1, %2, %0;" : "+l"(acc) : "l"(a), "l"(b))

// ---------------- full-K projection: P_k = x @ W_k (fp32), 2 nodes/thread --------
__global__ void __launch_bounds__(128) proj_kernel(const float* __restrict__ x,
                                                   const float* __restrict__ cheb_w,
                                                   int k_offset) {
    __shared__ __align__(16) float Wsm[D_IN * 52];
    int tid = threadIdx.x;
    int k = blockIdx.y + k_offset;
    const float* W = cheb_w + (size_t)k * D_IN * D_HID;
    #pragma unroll 1
    for (int o = 0; o < D_HID; o++) Wsm[tid * 52 + o] = W[tid * D_HID + o];
    Wsm[tid * 52 + 50] = 0.0f;
    Wsm[tid * 52 + 51] = 0.0f;
    __syncthreads();

    int n0 = blockIdx.x * 256 + tid;
    int n1 = n0 + 128;
    bool v0 = n0 < N_NODES;
    bool v1 = n1 < N_NODES;

    unsigned long long acc0[26], acc1[26];
    #pragma unroll
    for (int p = 0; p < 26; p++) { acc0[p] = 0ull; acc1[p] = 0ull; }

    const float4* A0 = (const float4*)(x + (size_t)n0 * D_IN);
    const float4* A1 = (const float4*)(x + (size_t)n1 * D_IN);
    float4 z4 = make_float4(0.f, 0.f, 0.f, 0.f);
    float4 a0 = v0 ? __ldg(A0) : z4;
    float4 a1 = v1 ? __ldg(A1) : z4;

    #pragma unroll 1
    for (int ic = 0; ic < 32; ic++) {
        float4 a0n = z4, a1n = z4;
        if (ic < 31) {
            if (v0) a0n = __ldg(A0 + ic + 1);
            if (v1) a1n = __ldg(A1 + ic + 1);
        }
        float av0[4] = {a0.x, a0.y, a0.z, a0.w};
        float av1[4] = {a1.x, a1.y, a1.z, a1.w};
        #pragma unroll
        for (int j = 0; j < 4; j++) {
            unsigned long long a0p = pack2(av0[j], av0[j]);
            unsigned long long a1p = pack2(av1[j], av1[j]);
            const float4* wrow = (const float4*)(Wsm + (ic * 4 + j) * 52);
            #pragma unroll
            for (int q = 0; q < 13; q++) {
                float4 wv = wrow[q];
                unsigned long long w01 = pack2(wv.x, wv.y);
                unsigned long long w23 = pack2(wv.z, wv.w);
                FMA2(acc0[2 * q],     w01, a0p);
                FMA2(acc0[2 * q + 1], w23, a0p);
                FMA2(acc1[2 * q],     w01, a1p);
                FMA2(acc1[2 * q + 1], w23, a1p);
            }
        }
        a0 = a0n; a1 = a1n;
    }

    #pragma unroll
    for (int which = 0; which < 2; which++) {
        bool v = which ? v1 : v0;
        int n = which ? n1 : n0;
        unsigned long long* acc = which ? acc1 : acc0;
        if (!v) continue;
        float* dst = g_P + ((size_t)k * N_NODES + n) * STRIDE;
        #pragma unroll
        for (int q = 0; q < 12; q++) {
            float x0, x1, x2, x3;
            unpack2(acc[2 * q], x0, x1);
            unpack2(acc[2 * q + 1], x2, x3);
            ((float4*)dst)[q] = make_float4(x0, x1, x2, x3);
        }
        float x0, x1; unpack2(acc[24], x0, x1);
        ((float2*)dst)[24] = make_float2(x0, x1);
    }
}

// ---------------- half-K partial projection for k=3,4, y-packed -------------------
// blockIdx.y: 0..3 -> (k, half) = (3 + y/2, y%2).
// half 0 -> g_P[k]; half 1 -> g_Pb[k-3].
__global__ void __launch_bounds__(128) proj_half_kernel(const float* __restrict__ x,
                                                        const float* __restrict__ cheb_w) {
    __shared__ __align__(16) float Wsm[64 * 52];
    int tid = threadIdx.x;
    int k = 3 + (blockIdx.y >> 1);
    int half = blockIdx.y & 1;
    const float* W = cheb_w + ((size_t)k * D_IN + half * 64) * D_HID;
    if (tid < 64) {
        #pragma unroll 1
        for (int o = 0; o < D_HID; o++) Wsm[tid * 52 + o] = W[tid * D_HID + o];
        Wsm[tid * 52 + 50] = 0.0f;
        Wsm[tid * 52 + 51] = 0.0f;
    }
    __syncthreads();

    int n0 = blockIdx.x * 256 + tid;
    int n1 = n0 + 128;
    bool v0 = n0 < N_NODES;
    bool v1 = n1 < N_NODES;

    unsigned long long acc0[26], acc1[26];
    #pragma unroll
    for (int p = 0; p < 26; p++) { acc0[p] = 0ull; acc1[p] = 0ull; }

    const float4* A0 = (const float4*)(x + (size_t)n0 * D_IN + half * 64);
    const float4* A1 = (const float4*)(x + (size_t)n1 * D_IN + half * 64);
    float4 z4 = make_float4(0.f, 0.f, 0.f, 0.f);
    float4 a0 = v0 ? __ldg(A0) : z4;
    float4 a1 = v1 ? __ldg(A1) : z4;

    #pragma unroll 1
    for (int ic = 0; ic < 16; ic++) {
        float4 a0n = z4, a1n = z4;
        if (ic < 15) {
            if (v0) a0n = __ldg(A0 + ic + 1);
            if (v1) a1n = __ldg(A1 + ic + 1);
        }
        float av0[4] = {a0.x, a0.y, a0.z, a0.w};
        float av1[4] = {a1.x, a1.y, a1.z, a1.w};
        #pragma unroll
        for (int j = 0; j < 4; j++) {
            unsigned long long a0p = pack2(av0[j], av0[j]);
            unsigned long long a1p = pack2(av1[j], av1[j]);
            const float4* wrow = (const float4*)(Wsm + (ic * 4 + j) * 52);
            #pragma unroll
            for (int q = 0; q < 13; q++) {
                float4 wv = wrow[q];
                unsigned long long w01 = pack2(wv.x, wv.y);
                unsigned long long w23 = pack2(wv.z, wv.w);
                FMA2(acc0[2 * q],     w01, a0p);
                FMA2(acc0[2 * q + 1], w23, a0p);
                FMA2(acc1[2 * q],     w01, a1p);
                FMA2(acc1[2 * q + 1], w23, a1p);
            }
        }
        a0 = a0n; a1 = a1n;
    }

    float* base = half ? (g_Pb + (size_t)(k - 3) * N_NODES * STRIDE)
                       : (g_P  + (size_t)k * N_NODES * STRIDE);
    #pragma unroll
    for (int which = 0; which < 2; which++) {
        bool v = which ? v1 : v0;
        int n = which ? n1 : n0;
        unsigned long long* acc = which ? acc1 : acc0;
        if (!v) continue;
        float* dst = base + (size_t)n * STRIDE;
        #pragma unroll
        for (int q = 0; q < 12; q++) {
            float x0, x1, x2, x3;
            unpack2(acc[2 * q], x0, x1);
            unpack2(acc[2 * q + 1], x2, x3);
            ((float4*)dst)[q] = make_float4(x0, x1, x2, x3);
        }
        float x0, x1; unpack2(acc[24], x0, x1);
        ((float2*)dst)[24] = make_float2(x0, x1);
    }
}

// ---------------- weightless gather accumulate: uint16 bucket, aligned bursts -----
__device__ __forceinline__ void row_sum_h(const __half2* __restrict__ src,
                                          const unsigned short* __restrict__ row,
                                          int deg, bool act, int lane,
                                          float& Sx, float& Sy) {
    float ax0 = 0.f, ay0 = 0.f, ax1 = 0.f, ay1 = 0.f;
    int i = 0;
    #pragma unroll 1
    for (; i + 8 <= deg; i += 8) {
        uint4 cp = __ldg((const uint4*)(row + i));       // 8 cols, 16B aligned
        unsigned c[8];
        c[0] = cp.x & 0xffffu; c[1] = cp.x >> 16;
        c[2] = cp.y & 0xffffu; c[3] = cp.y >> 16;
        c[4] = cp.z & 0xffffu; c[5] = cp.z >> 16;
        c[6] = cp.w & 0xffffu; c[7] = cp.w >> 16;
        if (act) {
            __half2 v[8];
            #pragma unroll
            for (int u = 0; u < 8; u++)
                v[u] = __ldcg((__half2*)(src + (size_t)c[u] * HSTRIDE + lane));
            #pragma unroll
            for (int u = 0; u < 8; u++) {
                float2 vf = __half22float2(v[u]);
                if (u & 1) { ax1 += vf.x; ay1 += vf.y; }
                else       { ax0 += vf.x; ay0 += vf.y; }
            }
        }
    }
    if (deg - i >= 4) {
        uint2 cp = __ldg((const uint2*)(row + i));       // 8B aligned
        unsigned c[4];
        c[0] = cp.x & 0xffffu; c[1] = cp.x >> 16;
        c[2] = cp.y & 0xffffu; c[3] = cp.y >> 16;
        if (act) {
            #pragma unroll
            for (int u = 0; u < 4; u++) {
                float2 vf = __half22float2(
                    __ldcg((__half2*)(src + (size_t)c[u] * HSTRIDE + lane)));
                if (u & 1) { ax1 += vf.x; ay1 += vf.y; }
                else       { ax0 += vf.x; ay0 += vf.y; }
            }
        }
        i += 4;
    }
    if (deg - i >= 2) {
        unsigned cp = __ldg((const unsigned*)(row + i)); // 4B aligned
        unsigned c0 = cp & 0xffffu, c1 = cp >> 16;
        if (act) {
            float2 v0 = __half22float2(__ldcg((__half2*)(src + (size_t)c0 * HSTRIDE + lane)));
            float2 v1 = __half22float2(__ldcg((__half2*)(src + (size_t)c1 * HSTRIDE + lane)));
            ax0 += v0.x; ay0 += v0.y;
            ax1 += v1.x; ay1 += v1.y;
        }
        i += 2;
    }
    if (i < deg) {
        unsigned c = __ldg(row + i);
        if (act) {
            float2 v = __half22float2(__ldcg((__half2*)(src + (size_t)c * HSTRIDE + lane)));
            ax0 += v.x; ay0 += v.y;
        }
    }
    Sx = ax0 + ax1;
    Sy = ay0 + ay1;
}

// ------- Clenshaw prop: real = P (+Padd) - scale*dinv*S - sub; scaled = dinv*real
__global__ void __launch_bounds__(256) prop_b(const __half2* __restrict__ src,
                                              const float* __restrict__ P,
                                              const float* __restrict__ Padd,
                                              const __half2* __restrict__ subH,
                                              const float* __restrict__ subF,
                                              float scale,
                                              __half2* __restrict__ dstR,
                                              __half2* __restrict__ dstS) {
    int gw = (blockIdx.x * blockDim.x + threadIdx.x) >> 5;
    int lane = threadIdx.x & 31;
    if (gw >= N_NODES) return;
    int deg = __ldg(&g_cursor[gw]);
    if (deg > CAP) deg = CAP;
    const unsigned short* row = g_bucket + (size_t)gw * CAP;
    const bool act = lane < 25;
    float Sx, Sy;
    row_sum_h(src, row, deg, act, lane, Sx, Sy);

    if (act) {
        float di = __ldg(&g_dinv[gw]);
        float2 p = __ldg((const float2*)P + (size_t)gw * (STRIDE / 2) + lane);
        float sdi = scale * di;
        float rx = p.x - sdi * Sx;
        float ry = p.y - sdi * Sy;
        if (Padd) {
            float2 pa = __ldg((const float2*)Padd + (size_t)gw * (STRIDE / 2) + lane);
            rx += pa.x; ry += pa.y;
        }
        if (subH) {
            float2 sb = __half22float2(__ldg(subH + (size_t)gw * HSTRIDE + lane));
            rx -= sb.x; ry -= sb.y;
        }
        if (subF) {
            float2 sb = __ldg((const float2*)subF + (size_t)gw * (STRIDE / 2) + lane);
            rx -= sb.x; ry -= sb.y;
        }
        size_t off = (size_t)gw * HSTRIDE + lane;
        if (dstR) dstR[off] = __floats2half2_rn(rx, ry);
        dstS[off] = __floats2half2_rn(di * rx, di * ry);
    }
}

// ---------------- last prop fused with head ----------------
__global__ void __launch_bounds__(256) prop_head(const __half2* __restrict__ src,
                                                 const float* __restrict__ P,
                                                 const __half2* __restrict__ subH,
                                                 const float* __restrict__ cheb_b,
                                                 const float* __restrict__ fc_w,
                                                 const float* __restrict__ fc_b,
                                                 float* __restrict__ out) {
    __shared__ __align__(8) float s_fcwT[D_OUT * 52];
    __shared__ float s_b[D_HID];
    __shared__ float s_fcb[D_OUT];
    int tid = threadIdx.x;
    for (int i = tid; i < D_HID * D_OUT; i += blockDim.x) {
        int j = i / D_OUT, o = i % D_OUT;
        s_fcwT[o * 52 + j] = fc_w[i];
    }
    if (tid < D_OUT) { s_fcwT[tid * 52 + 50] = 0.f; s_fcwT[tid * 52 + 51] = 0.f; }
    if (tid < D_HID) s_b[tid] = cheb_b[tid];
    if (tid < D_OUT) s_fcb[tid] = fc_b[tid];
    __syncthreads();

    int gw = (blockIdx.x * blockDim.x + tid) >> 5;
    int lane = tid & 31;
    if (gw >= N_NODES) return;
    int deg = __ldg(&g_cursor[gw]);
    if (deg > CAP) deg = CAP;
    const unsigned short* row = g_bucket + (size_t)gw * CAP;
    const bool act = lane < 25;
    float Sx, Sy;
    row_sum_h(src, row, deg, act, lane, Sx, Sy);

    float l[D_OUT];
    if (act) {
        float di = __ldg(&g_dinv[gw]);
        float2 p  = __ldg((const float2*)P + (size_t)gw * (STRIDE / 2) + lane);
        float2 sb = __half22float2(__ldg(subH + (size_t)gw * HSTRIDE + lane));
        float hx = fmaxf(p.x - di * Sx - sb.x + s_b[2 * lane],     0.0f);  // scale = 1
        float hy = fmaxf(p.y - di * Sy - sb.y + s_b[2 * lane + 1], 0.0f);
        #pragma unroll
        for (int o = 0; o < D_OUT; o++) {
            float2 w2 = ((const float2*)(s_fcwT + o * 52))[lane];
            l[o] = hx * w2.x + hy * w2.y;
        }
    } else {
        #pragma unroll
        for (int o = 0; o < D_OUT; o++) l[o] = 0.0f;
    }

    #pragma unroll
    for (int offm = 16; offm > 0; offm >>= 1) {
        #pragma unroll
        for (int o = 0; o < D_OUT; o++)
            l[o] += __shfl_xor_sync(0xffffffffu, l[o], offm);
    }

    if (lane == 0) {
        #pragma unroll
        for (int o = 0; o < D_OUT; o++) l[o] += s_fcb[o];
        float m = l[0];
        #pragma unroll
        for (int o = 1; o < D_OUT; o++) m = fmaxf(m, l[o]);
        float ssum = 0.0f;
        #pragma unroll
        for (int o = 0; o < D_OUT; o++) ssum += expf(l[o] - m);
        float lse = m + logf(ssum);
        float* orow = out + (size_t)gw * D_OUT;
        #pragma unroll
        for (int o = 0; o < D_OUT; o++) orow[o] = l[o] - lse;
    }
}

// ---------------- launch ----------------
extern "C" void kernel_launch(void* const* d_in, const int* in_sizes, int n_in,
                              void* d_out, int out_size) {
    const float* x      = (const float*)d_in[0];
    const void*  ei     = d_in[1];
    const float* cheb_w = (const float*)d_in[2];
    const float* cheb_b = (const float*)d_in[3];
    const float* fc_w   = (const float*)d_in[4];
    const float* fc_b   = (const float*)d_in[5];
    float* out = (float*)d_out;

    float *P, *Pb;
    __half2 *P4s, *b3s, *b3r, *b2s, *b2r, *b1s;
    cudaGetSymbolAddress((void**)&P,   g_P);
    cudaGetSymbolAddress((void**)&Pb,  g_Pb);
    cudaGetSymbolAddress((void**)&P4s, g_P4s);
    cudaGetSymbolAddress((void**)&b3s, g_b3s);
    cudaGetSymbolAddress((void**)&b3r, g_b3r);
    cudaGetSymbolAddress((void**)&b2s, g_b2s);
    cudaGetSymbolAddress((void**)&b2r, g_b2r);
    cudaGetSymbolAddress((void**)&b1s, g_b1s);
    const size_t PS = (size_t)N_NODES * STRIDE;
    float* P0  = P  + 0 * PS;
    float* P1  = P  + 1 * PS;
    float* P2  = P  + 2 * PS;
    float* P3  = P  + 3 * PS;
    float* P4  = P  + 4 * PS;
    float* P3b = Pb + 0 * PS;

    const int TB = 256;
    const int NODE_BLK = (N_NODES + TB - 1) / TB;
    const int HALF_EDGE_BLK = (N_EDGES / 2 + TB - 1) / TB;
    const long long PT = (long long)N_NODES * 32;
    const int PROP_BLK = (int)((PT + TB - 1) / TB);
    const int PROJ_GX = (N_NODES + 255) / 256;   // 196 blocks, 2 nodes/thread

    static cudaStream_t s_proj = nullptr;
    static cudaEvent_t evA = nullptr, ev2 = nullptr, ev1 = nullptr, ev0 = nullptr, ev_fork = nullptr;
    static int use_async = -1;
    if (use_async < 0) {
        bool ok = (cudaStreamCreateWithFlags(&s_proj, cudaStreamNonBlocking) == cudaSuccess);
        ok = ok && (cudaEventCreateWithFlags(&ev_fork, cudaEventDisableTiming) == cudaSuccess);
        ok = ok && (cudaEventCreateWithFlags(&evA, cudaEventDisableTiming) == cudaSuccess);
        ok = ok && (cudaEventCreateWithFlags(&ev2, cudaEventDisableTiming) == cudaSuccess);
        ok = ok && (cudaEventCreateWithFlags(&ev1, cudaEventDisableTiming) == cudaSuccess);
        ok = ok && (cudaEventCreateWithFlags(&ev0, cudaEventDisableTiming) == cudaSuccess);
        use_async = ok ? 1 : 0;
    }

    if (use_async) {
        // ---- fork: k=3,4 as one y-packed half-K launch (784 blocks), then k=2,1,0 ----
        cudaEventRecord(ev_fork, 0);
        cudaStreamWaitEvent(s_proj, ev_fork, 0);
        proj_half_kernel<<<dim3(PROJ_GX, 4), 128, 0, s_proj>>>(x, cheb_w);
        cudaEventRecord(evA, s_proj);
        proj_kernel<<<dim3(PROJ_GX, 1), 128, 0, s_proj>>>(x, cheb_w, 2);  // k=2
        cudaEventRecord(ev2, s_proj);
        proj_kernel<<<dim3(PROJ_GX, 1), 128, 0, s_proj>>>(x, cheb_w, 1);  // k=1
        cudaEventRecord(ev1, s_proj);
        proj_kernel<<<dim3(PROJ_GX, 1), 128, 0, s_proj>>>(x, cheb_w, 0);  // k=0
        cudaEventRecord(ev0, s_proj);

        // ---- single-pass bucket CSR (main stream, concurrent) ----
        init_kernel<<<NODE_BLK, TB>>>((const int*)ei);
        scatter_kernel<<<HALF_EDGE_BLK, TB>>>(ei);
        dinv_kernel<<<NODE_BLK, TB>>>();

        // ---- Clenshaw ----
        cudaStreamWaitEvent(0, evA, 0);
        scaleP4_kernel<<<PROP_BLK, TB>>>();   // P4 = P4a+P4b (fp32), P4s = D*P4 (fp16)
        prop_b<<<PROP_BLK, TB>>>(P4s, P3, P3b, nullptr, nullptr, 2.0f, b3r, b3s); // b3 = P3 + 2L P4
        cudaStreamWaitEvent(0, ev2, 0);
        prop_b<<<PROP_BLK, TB>>>(b3s, P2, nullptr, nullptr, P4, 2.0f, b2r, b2s);  // b2 = P2 + 2L b3 - P4
        cudaStreamWaitEvent(0, ev1, 0);
        prop_b<<<PROP_BLK, TB>>>(b2s, P1, nullptr, b3r, nullptr, 2.0f, nullptr, b1s); // b1 = P1 + 2L b2 - b3
        cudaStreamWaitEvent(0, ev0, 0);
        prop_head<<<PROP_BLK, TB>>>(b1s, P0, b2r, cheb_b, fc_w, fc_b, out);
    } else {
        // serial fallback
        init_kernel<<<NODE_BLK, TB>>>((const int*)ei);
        scatter_kernel<<<HALF_EDGE_BLK, TB>>>(ei);
        dinv_kernel<<<NODE_BLK, TB>>>();
        proj_half_kernel<<<dim3(PROJ_GX, 4), 128>>>(x, cheb_w);
        proj_kernel<<<dim3(PROJ_GX, 3), 128>>>(x, cheb_w, 0);  // k=0,1,2
        scaleP4_kernel<<<PROP_BLK, TB>>>();
        prop_b<<<PROP_BLK, TB>>>(P4s, P3, P3b, nullptr, nullptr, 2.0f, b3r, b3s);
        prop_b<<<PROP_BLK, TB>>>(b3s, P2, nullptr, nullptr, P4, 2.0f, b2r, b2s);
        prop_b<<<PROP_BLK, TB>>>(b2s, P1, nullptr, b3r, nullptr, 2.0f, nullptr, b1s);
        prop_head<<<PROP_BLK, TB>>>(b1s, P0, b2r, cheb_b, fc_w, fc_b, out);
    }
}

// round 16
// speedup vs baseline: 1.1943x; 1.0185x over previous
#include <cuda_runtime.h>
#include <cuda_fp16.h>
#include <math.h>

#define N_NODES 50000
#define N_EDGES 1600000
#define D_IN    128
#define D_HID   50
#define D_OUT   10
#define STRIDE  64   // fp32 row stride (floats) for P0..P4
#define HSTRIDE 32   // fp16 row stride (half2 units) = 128 bytes
#define CAP     128  // bucket capacity per row (17-sigma headroom over mean 32)

// ---------------- static scratch ----------------
__device__ float g_P [(size_t)5 * N_NODES * STRIDE];              // P0..P4 fp32
__device__ __align__(128) __half2 g_P4s[(size_t)N_NODES * HSTRIDE];  // D*P4
__device__ __align__(128) __half2 g_b3s[(size_t)N_NODES * HSTRIDE];  // D*b3
__device__ __align__(128) __half2 g_b3r[(size_t)N_NODES * HSTRIDE];  // b3 real
__device__ __align__(128) __half2 g_b2s[(size_t)N_NODES * HSTRIDE];
__device__ __align__(128) __half2 g_b2r[(size_t)N_NODES * HSTRIDE];
__device__ __align__(128) __half2 g_b1s[(size_t)N_NODES * HSTRIDE];
__device__ int   g_cursor[N_NODES];                                // degree counters
__device__ float g_dinv  [N_NODES];
__device__ __align__(16) unsigned short g_bucket[(size_t)N_NODES * CAP];
__device__ int   g_is64;

// ---------------- init: zero cursors + dtype detect ----------------
__global__ void init_kernel(const int* __restrict__ ei32) {
    int i = blockIdx.x * blockDim.x + threadIdx.x;
    if (i < N_NODES) g_cursor[i] = 0;
    if (blockIdx.x == 0) {
        __shared__ int nz;
        if (threadIdx.x == 0) nz = 0;
        __syncthreads();
        // int64 edge_index with values<50000 has all-zero high words
        if (ei32[2 * threadIdx.x + 1] != 0) atomicExch(&nz, 1);
        __syncthreads();
        if (threadIdx.x == 0) g_is64 = (nz == 0) ? 1 : 0;
    }
}

// ---------------- scatter: single-pass bucket CSR (cols only), 4 edges/thread ----
__global__ void scatter_kernel(const void* __restrict__ ei) {
    int t = blockIdx.x * blockDim.x + threadIdx.x;
    if (t >= N_EDGES / 4) return;
    int r[4], c[4];
    if (g_is64) {
        const longlong2* rp = (const longlong2*)ei + 2 * t;
        const longlong2* cp = (const longlong2*)ei + (N_EDGES / 2) + 2 * t;
        longlong2 rv0 = __ldg(rp);
        longlong2 rv1 = __ldg(rp + 1);
        longlong2 cv0 = __ldg(cp);
        longlong2 cv1 = __ldg(cp + 1);
        r[0] = (int)rv0.x; r[1] = (int)rv0.y; r[2] = (int)rv1.x; r[3] = (int)rv1.y;
        c[0] = (int)cv0.x; c[1] = (int)cv0.y; c[2] = (int)cv1.x; c[3] = (int)cv1.y;
    } else {
        int4 rv = __ldg((const int4*)ei + t);
        int4 cv = __ldg((const int4*)((const int*)ei + N_EDGES) + t);
        r[0] = rv.x; r[1] = rv.y; r[2] = rv.z; r[3] = rv.w;
        c[0] = cv.x; c[1] = cv.y; c[2] = cv.z; c[3] = cv.w;
    }
    #pragma unroll
    for (int u = 0; u < 4; u++) {
        int p = atomicAdd(&g_cursor[r[u]], 1);
        if (p < CAP) g_bucket[(size_t)r[u] * CAP + p] = (unsigned short)c[u];
    }
}

// ---------------- dinv from the post-scatter cursors ----------------
__global__ void dinv_kernel() {
    int n = blockIdx.x * blockDim.x + threadIdx.x;
    if (n >= N_NODES) return;
    int d = g_cursor[n];
    g_dinv[n] = (d > 0) ? rsqrtf((float)d) : 0.0f;
}

// ---------------- scale P4 -> D*P4 (fp16), warp per row ----------------
__global__ void __launch_bounds__(256) scaleP4_kernel() {
    int gw = (blockIdx.x * blockDim.x + threadIdx.x) >> 5;
    int lane = threadIdx.x & 31;
    if (gw >= N_NODES || lane >= 25) return;
    float di = __ldg(&g_dinv[gw]);
    float2 p = __ldg((const float2*)(g_P + ((size_t)4 * N_NODES + gw) * STRIDE) + lane);
    g_P4s[(size_t)gw * HSTRIDE + lane] = __floats2half2_rn(di * p.x, di * p.y);
}

// ---------------- f32x2 helpers ----------------
__device__ __forceinline__ unsigned long long pack2(float lo, float hi) {
    unsigned long long r;
    asm("mov.b64 %0, {%1, %2};" : "=l"(r) : "f"(lo), "f"(hi));
    return r;
}
__device__ __forceinline__ void unpack2(unsigned long long v, float& lo, float& hi) {
    asm("mov.b64 {%0, %1}, %2;" : "=f"(lo), "=f"(hi) : "l"(v));
}
#define FMA2(acc, a, b) asm("fma.rn.f32x2 %0, %1, %2, %0;" : "+l"(acc) : "l"(a), "l"(b))

// ---------------- projection: P_k = x @ W_k (fp32 out), 2 nodes/thread -----------
__global__ void __launch_bounds__(128) proj_kernel(const float* __restrict__ x,
                                                   const float* __restrict__ cheb_w,
                                                   int k_offset) {
    __shared__ __align__(16) float Wsm[D_IN * 52];
    int tid = threadIdx.x;
    int k = blockIdx.y + k_offset;
    const float* W = cheb_w + (size_t)k * D_IN * D_HID;
    #pragma unroll 1
    for (int o = 0; o < D_HID; o++) Wsm[tid * 52 + o] = W[tid * D_HID + o];
    Wsm[tid * 52 + 50] = 0.0f;
    Wsm[tid * 52 + 51] = 0.0f;
    __syncthreads();

    int n0 = blockIdx.x * 256 + tid;
    int n1 = n0 + 128;
    bool v0 = n0 < N_NODES;
    bool v1 = n1 < N_NODES;

    unsigned long long acc0[26], acc1[26];
    #pragma unroll
    for (int p = 0; p < 26; p++) { acc0[p] = 0ull; acc1[p] = 0ull; }

    const float4* A0 = (const float4*)(x + (size_t)n0 * D_IN);
    const float4* A1 = (const float4*)(x + (size_t)n1 * D_IN);
    float4 z4 = make_float4(0.f, 0.f, 0.f, 0.f);
    float4 a0 = v0 ? __ldg(A0) : z4;
    float4 a1 = v1 ? __ldg(A1) : z4;

    #pragma unroll 1
    for (int ic = 0; ic < 32; ic++) {
        float4 a0n = z4, a1n = z4;
        if (ic < 31) {
            if (v0) a0n = __ldg(A0 + ic + 1);
            if (v1) a1n = __ldg(A1 + ic + 1);
        }
        float av0[4] = {a0.x, a0.y, a0.z, a0.w};
        float av1[4] = {a1.x, a1.y, a1.z, a1.w};
        #pragma unroll
        for (int j = 0; j < 4; j++) {
            unsigned long long a0p = pack2(av0[j], av0[j]);
            unsigned long long a1p = pack2(av1[j], av1[j]);
            const float4* wrow = (const float4*)(Wsm + (ic * 4 + j) * 52);
            #pragma unroll
            for (int q = 0; q < 13; q++) {
                float4 wv = wrow[q];
                unsigned long long w01 = pack2(wv.x, wv.y);
                unsigned long long w23 = pack2(wv.z, wv.w);
                FMA2(acc0[2 * q],     w01, a0p);
                FMA2(acc0[2 * q + 1], w23, a0p);
                FMA2(acc1[2 * q],     w01, a1p);
                FMA2(acc1[2 * q + 1], w23, a1p);
            }
        }
        a0 = a0n; a1 = a1n;
    }

    #pragma unroll
    for (int which = 0; which < 2; which++) {
        bool v = which ? v1 : v0;
        int n = which ? n1 : n0;
        unsigned long long* acc = which ? acc1 : acc0;
        if (!v) continue;
        float* dst = g_P + ((size_t)k * N_NODES + n) * STRIDE;
        #pragma unroll
        for (int q = 0; q < 12; q++) {
            float x0, x1, x2, x3;
            unpack2(acc[2 * q], x0, x1);
            unpack2(acc[2 * q + 1], x2, x3);
            ((float4*)dst)[q] = make_float4(x0, x1, x2, x3);
        }
        float x0, x1; unpack2(acc[24], x0, x1);
        ((float2*)dst)[24] = make_float2(x0, x1);
    }
}

// ---------------- weightless gather accumulate: uint16 bucket, aligned bursts -----
__device__ __forceinline__ void row_sum_h(const __half2* __restrict__ src,
                                          const unsigned short* __restrict__ row,
                                          int deg, bool act, int lane,
                                          float& Sx, float& Sy) {
    float ax0 = 0.f, ay0 = 0.f, ax1 = 0.f, ay1 = 0.f;
    int i = 0;
    #pragma unroll 1
    for (; i + 8 <= deg; i += 8) {
        uint4 cp = __ldg((const uint4*)(row + i));       // 8 cols, 16B aligned
        unsigned c[8];
        c[0] = cp.x & 0xffffu; c[1] = cp.x >> 16;
        c[2] = cp.y & 0xffffu; c[3] = cp.y >> 16;
        c[4] = cp.z & 0xffffu; c[5] = cp.z >> 16;
        c[6] = cp.w & 0xffffu; c[7] = cp.w >> 16;
        if (act) {
            __half2 v[8];
            #pragma unroll
            for (int u = 0; u < 8; u++)
                v[u] = __ldcg((__half2*)(src + (size_t)c[u] * HSTRIDE + lane));
            #pragma unroll
            for (int u = 0; u < 8; u++) {
                float2 vf = __half22float2(v[u]);
                if (u & 1) { ax1 += vf.x; ay1 += vf.y; }
                else       { ax0 += vf.x; ay0 += vf.y; }
            }
        }
    }
    if (deg - i >= 4) {
        uint2 cp = __ldg((const uint2*)(row + i));       // 8B aligned
        unsigned c[4];
        c[0] = cp.x & 0xffffu; c[1] = cp.x >> 16;
        c[2] = cp.y & 0xffffu; c[3] = cp.y >> 16;
        if (act) {
            #pragma unroll
            for (int u = 0; u < 4; u++) {
                float2 vf = __half22float2(
                    __ldcg((__half2*)(src + (size_t)c[u] * HSTRIDE + lane)));
                if (u & 1) { ax1 += vf.x; ay1 += vf.y; }
                else       { ax0 += vf.x; ay0 += vf.y; }
            }
        }
        i += 4;
    }
    if (deg - i >= 2) {
        unsigned cp = __ldg((const unsigned*)(row + i)); // 4B aligned
        unsigned c0 = cp & 0xffffu, c1 = cp >> 16;
        if (act) {
            float2 v0 = __half22float2(__ldcg((__half2*)(src + (size_t)c0 * HSTRIDE + lane)));
            float2 v1 = __half22float2(__ldcg((__half2*)(src + (size_t)c1 * HSTRIDE + lane)));
            ax0 += v0.x; ay0 += v0.y;
            ax1 += v1.x; ay1 += v1.y;
        }
        i += 2;
    }
    if (i < deg) {
        unsigned c = __ldg(row + i);
        if (act) {
            float2 v = __half22float2(__ldcg((__half2*)(src + (size_t)c * HSTRIDE + lane)));
            ax0 += v.x; ay0 += v.y;
        }
    }
    Sx = ax0 + ax1;
    Sy = ay0 + ay1;
}

// ---------------- Clenshaw prop: real = P - scale*dinv*S - sub; scaled = dinv*real
__global__ void __launch_bounds__(256) prop_b(const __half2* __restrict__ src,
                                              const float* __restrict__ P,
                                              const __half2* __restrict__ subH,
                                              const float* __restrict__ subF,
                                              float scale,
                                              __half2* __restrict__ dstR,
                                              __half2* __restrict__ dstS) {
    int gw = (blockIdx.x * blockDim.x + threadIdx.x) >> 5;
    int lane = threadIdx.x & 31;
    if (gw >= N_NODES) return;
    int deg = __ldg(&g_cursor[gw]);
    if (deg > CAP) deg = CAP;
    const unsigned short* row = g_bucket + (size_t)gw * CAP;
    const bool act = lane < 25;
    float Sx, Sy;
    row_sum_h(src, row, deg, act, lane, Sx, Sy);

    if (act) {
        float di = __ldg(&g_dinv[gw]);
        float2 p = __ldg((const float2*)P + (size_t)gw * (STRIDE / 2) + lane);
        float sdi = scale * di;
        float rx = p.x - sdi * Sx;
        float ry = p.y - sdi * Sy;
        if (subH) {
            float2 sb = __half22float2(__ldg(subH + (size_t)gw * HSTRIDE + lane));
            rx -= sb.x; ry -= sb.y;
        }
        if (subF) {
            float2 sb = __ldg((const float2*)subF + (size_t)gw * (STRIDE / 2) + lane);
            rx -= sb.x; ry -= sb.y;
        }
        size_t off = (size_t)gw * HSTRIDE + lane;
        if (dstR) dstR[off] = __floats2half2_rn(rx, ry);
        dstS[off] = __floats2half2_rn(di * rx, di * ry);
    }
}

// ---------------- last prop fused with head ----------------
__global__ void __launch_bounds__(256) prop_head(const __half2* __restrict__ src,
                                                 const float* __restrict__ P,
                                                 const __half2* __restrict__ subH,
                                                 const float* __restrict__ cheb_b,
                                                 const float* __restrict__ fc_w,
                                                 const float* __restrict__ fc_b,
                                                 float* __restrict__ out) {
    __shared__ __align__(8) float s_fcwT[D_OUT * 52];
    __shared__ float s_b[D_HID];
    __shared__ float s_fcb[D_OUT];
    int tid = threadIdx.x;
    for (int i = tid; i < D_HID * D_OUT; i += blockDim.x) {
        int j = i / D_OUT, o = i % D_OUT;
        s_fcwT[o * 52 + j] = fc_w[i];
    }
    if (tid < D_OUT) { s_fcwT[tid * 52 + 50] = 0.f; s_fcwT[tid * 52 + 51] = 0.f; }
    if (tid < D_HID) s_b[tid] = cheb_b[tid];
    if (tid < D_OUT) s_fcb[tid] = fc_b[tid];
    __syncthreads();

    int gw = (blockIdx.x * blockDim.x + tid) >> 5;
    int lane = tid & 31;
    if (gw >= N_NODES) return;
    int deg = __ldg(&g_cursor[gw]);
    if (deg > CAP) deg = CAP;
    const unsigned short* row = g_bucket + (size_t)gw * CAP;
    const bool act = lane < 25;
    float Sx, Sy;
    row_sum_h(src, row, deg, act, lane, Sx, Sy);

    float l[D_OUT];
    if (act) {
        float di = __ldg(&g_dinv[gw]);
        float2 p  = __ldg((const float2*)P + (size_t)gw * (STRIDE / 2) + lane);
        float2 sb = __half22float2(__ldg(subH + (size_t)gw * HSTRIDE + lane));
        float hx = fmaxf(p.x - di * Sx - sb.x + s_b[2 * lane],     0.0f);  // scale = 1
        float hy = fmaxf(p.y - di * Sy - sb.y + s_b[2 * lane + 1], 0.0f);
        #pragma unroll
        for (int o = 0; o < D_OUT; o++) {
            float2 w2 = ((const float2*)(s_fcwT + o * 52))[lane];
            l[o] = hx * w2.x + hy * w2.y;
        }
    } else {
        #pragma unroll
        for (int o = 0; o < D_OUT; o++) l[o] = 0.0f;
    }

    #pragma unroll
    for (int offm = 16; offm > 0; offm >>= 1) {
        #pragma unroll
        for (int o = 0; o < D_OUT; o++)
            l[o] += __shfl_xor_sync(0xffffffffu, l[o], offm);
    }

    if (lane == 0) {
        #pragma unroll
        for (int o = 0; o < D_OUT; o++) l[o] += s_fcb[o];
        float m = l[0];
        #pragma unroll
        for (int o = 1; o < D_OUT; o++) m = fmaxf(m, l[o]);
        float ssum = 0.0f;
        #pragma unroll
        for (int o = 0; o < D_OUT; o++) ssum += expf(l[o] - m);
        float lse = m + logf(ssum);
        float* orow = out + (size_t)gw * D_OUT;
        #pragma unroll
        for (int o = 0; o < D_OUT; o++) orow[o] = l[o] - lse;
    }
}

// ---------------- launch ----------------
extern "C" void kernel_launch(void* const* d_in, const int* in_sizes, int n_in,
                              void* d_out, int out_size) {
    const float* x      = (const float*)d_in[0];
    const void*  ei     = d_in[1];
    const float* cheb_w = (const float*)d_in[2];
    const float* cheb_b = (const float*)d_in[3];
    const float* fc_w   = (const float*)d_in[4];
    const float* fc_b   = (const float*)d_in[5];
    float* out = (float*)d_out;

    float* P;
    __half2 *P4s, *b3s, *b3r, *b2s, *b2r, *b1s;
    cudaGetSymbolAddress((void**)&P,   g_P);
    cudaGetSymbolAddress((void**)&P4s, g_P4s);
    cudaGetSymbolAddress((void**)&b3s, g_b3s);
    cudaGetSymbolAddress((void**)&b3r, g_b3r);
    cudaGetSymbolAddress((void**)&b2s, g_b2s);
    cudaGetSymbolAddress((void**)&b2r, g_b2r);
    cudaGetSymbolAddress((void**)&b1s, g_b1s);
    const size_t PS = (size_t)N_NODES * STRIDE;
    float* P0 = P + 0 * PS;
    float* P1 = P + 1 * PS;
    float* P2 = P + 2 * PS;
    float* P3 = P + 3 * PS;
    float* P4 = P + 4 * PS;

    const int TB = 256;
    const int NODE_BLK = (N_NODES + TB - 1) / TB;
    const int QUART_EDGE_BLK = (N_EDGES / 4 + TB - 1) / TB;
    const long long PT = (long long)N_NODES * 32;
    const int PROP_BLK = (int)((PT + TB - 1) / TB);
    const int PROJ_GX = (N_NODES + 255) / 256;   // 196 blocks, 2 nodes/thread

    static cudaStream_t s_proj = nullptr;
    static cudaEvent_t evA = nullptr, ev2 = nullptr, ev1 = nullptr, ev0 = nullptr, ev_fork = nullptr;
    static int use_async = -1;
    if (use_async < 0) {
        bool ok = (cudaStreamCreateWithFlags(&s_proj, cudaStreamNonBlocking) == cudaSuccess);
        ok = ok && (cudaEventCreateWithFlags(&ev_fork, cudaEventDisableTiming) == cudaSuccess);
        ok = ok && (cudaEventCreateWithFlags(&evA, cudaEventDisableTiming) == cudaSuccess);
        ok = ok && (cudaEventCreateWithFlags(&ev2, cudaEventDisableTiming) == cudaSuccess);
        ok = ok && (cudaEventCreateWithFlags(&ev1, cudaEventDisableTiming) == cudaSuccess);
        ok = ok && (cudaEventCreateWithFlags(&ev0, cudaEventDisableTiming) == cudaSuccess);
        use_async = ok ? 1 : 0;
    }

    if (use_async) {
        // ---- fork: pipelined projections on side stream (R10 champion topology) ----
        cudaEventRecord(ev_fork, 0);
        cudaStreamWaitEvent(s_proj, ev_fork, 0);
        proj_kernel<<<dim3(PROJ_GX, 2), 128, 0, s_proj>>>(x, cheb_w, 3);  // k=3,4
        cudaEventRecord(evA, s_proj);
        proj_kernel<<<dim3(PROJ_GX, 1), 128, 0, s_proj>>>(x, cheb_w, 2);  // k=2
        cudaEventRecord(ev2, s_proj);
        proj_kernel<<<dim3(PROJ_GX, 1), 128, 0, s_proj>>>(x, cheb_w, 1);  // k=1
        cudaEventRecord(ev1, s_proj);
        proj_kernel<<<dim3(PROJ_GX, 1), 128, 0, s_proj>>>(x, cheb_w, 0);  // k=0
        cudaEventRecord(ev0, s_proj);

        // ---- single-pass bucket CSR (main stream, concurrent) ----
        init_kernel<<<NODE_BLK, TB>>>((const int*)ei);
        scatter_kernel<<<QUART_EDGE_BLK, TB>>>(ei);
        dinv_kernel<<<NODE_BLK, TB>>>();

        // ---- Clenshaw ----
        cudaStreamWaitEvent(0, evA, 0);
        scaleP4_kernel<<<PROP_BLK, TB>>>();                                   // P4s = D P4
        prop_b<<<PROP_BLK, TB>>>(P4s, P3, nullptr, nullptr, 2.0f, b3r, b3s);  // b3 = P3 + 2L P4
        cudaStreamWaitEvent(0, ev2, 0);
        prop_b<<<PROP_BLK, TB>>>(b3s, P2, nullptr, P4,      2.0f, b2r, b2s);  // b2 = P2 + 2L b3 - P4
        cudaStreamWaitEvent(0, ev1, 0);
        prop_b<<<PROP_BLK, TB>>>(b2s, P1, b3r,    nullptr,  2.0f, nullptr, b1s); // b1 = P1 + 2L b2 - b3
        cudaStreamWaitEvent(0, ev0, 0);
        prop_head<<<PROP_BLK, TB>>>(b1s, P0, b2r, cheb_b, fc_w, fc_b, out);
    } else {
        // serial fallback
        init_kernel<<<NODE_BLK, TB>>>((const int*)ei);
        scatter_kernel<<<QUART_EDGE_BLK, TB>>>(ei);
        dinv_kernel<<<NODE_BLK, TB>>>();
        proj_kernel<<<dim3(PROJ_GX, 5), 128>>>(x, cheb_w, 0);
        scaleP4_kernel<<<PROP_BLK, TB>>>();
        prop_b<<<PROP_BLK, TB>>>(P4s, P3, nullptr, nullptr, 2.0f, b3r, b3s);
        prop_b<<<PROP_BLK, TB>>>(b3s, P2, nullptr, P4,      2.0f, b2r, b2s);
        prop_b<<<PROP_BLK, TB>>>(b2s, P1, b3r,    nullptr,  2.0f, nullptr, b1s);
        prop_head<<<PROP_BLK, TB>>>(b1s, P0, b2r, cheb_b, fc_w, fc_b, out);
    }
}

// round 17
// speedup vs baseline: 1.2331x; 1.0325x over previous
#include <cuda_runtime.h>
#include <cuda_fp16.h>
#include <math.h>

#define N_NODES 50000
#define N_EDGES 1600000
#define D_IN    128
#define D_HID   50
#define D_OUT   10
#define STRIDE  64   // fp32 row stride (floats) for P0..P4
#define HSTRIDE 32   // fp16 row stride (half2 units) = 128 bytes
#define CAP     128  // bucket capacity per row (17-sigma headroom over mean 32)

// ---------------- static scratch ----------------
__device__ float g_P [(size_t)5 * N_NODES * STRIDE];              // P0..P4 fp32
__device__ __align__(128) __half2 g_P4s[(size_t)N_NODES * HSTRIDE];  // D*P4
__device__ __align__(128) __half2 g_b3s[(size_t)N_NODES * HSTRIDE];  // D*b3
__device__ __align__(128) __half2 g_b3r[(size_t)N_NODES * HSTRIDE];  // b3 real
__device__ __align__(128) __half2 g_b2s[(size_t)N_NODES * HSTRIDE];
__device__ __align__(128) __half2 g_b2r[(size_t)N_NODES * HSTRIDE];
__device__ __align__(128) __half2 g_b1s[(size_t)N_NODES * HSTRIDE];
__device__ int   g_cursor[N_NODES];                                // degree counters
__device__ float g_dinv  [N_NODES];
__device__ __align__(16) unsigned short g_bucket[(size_t)N_NODES * CAP];
__device__ int   g_is64;

// ---------------- init: zero cursors + dtype detect ----------------
__global__ void init_kernel(const int* __restrict__ ei32) {
    int i = blockIdx.x * blockDim.x + threadIdx.x;
    if (i < N_NODES) g_cursor[i] = 0;
    if (blockIdx.x == 0) {
        __shared__ int nz;
        if (threadIdx.x == 0) nz = 0;
        __syncthreads();
        // int64 edge_index with values<50000 has all-zero high words
        if (ei32[2 * threadIdx.x + 1] != 0) atomicExch(&nz, 1);
        __syncthreads();
        if (threadIdx.x == 0) g_is64 = (nz == 0) ? 1 : 0;
    }
}

// ---------------- scatter: single-pass bucket CSR (cols only), 2 edges/thread ----
__global__ void scatter_kernel(const void* __restrict__ ei) {
    int t = blockIdx.x * blockDim.x + threadIdx.x;
    if (t >= N_EDGES / 2) return;
    int r0, r1, c0, c1;
    if (g_is64) {
        longlong2 rv = __ldg((const longlong2*)ei + t);
        longlong2 cv = __ldg((const longlong2*)ei + (N_EDGES / 2) + t);
        r0 = (int)rv.x; r1 = (int)rv.y; c0 = (int)cv.x; c1 = (int)cv.y;
    } else {
        int2 rv = __ldg((const int2*)ei + t);
        int2 cv = __ldg((const int2*)ei + (N_EDGES / 2) + t);
        r0 = rv.x; r1 = rv.y; c0 = cv.x; c1 = cv.y;
    }
    int p0 = atomicAdd(&g_cursor[r0], 1);
    if (p0 < CAP) g_bucket[(size_t)r0 * CAP + p0] = (unsigned short)c0;
    int p1 = atomicAdd(&g_cursor[r1], 1);
    if (p1 < CAP) g_bucket[(size_t)r1 * CAP + p1] = (unsigned short)c1;
}

// ---------------- dinv from the post-scatter cursors ----------------
__global__ void dinv_kernel() {
    int n = blockIdx.x * blockDim.x + threadIdx.x;
    if (n >= N_NODES) return;
    int d = g_cursor[n];
    g_dinv[n] = (d > 0) ? rsqrtf((float)d) : 0.0f;
}

// ---------------- scale P4 -> D*P4 (fp16), warp per row ----------------
__global__ void __launch_bounds__(256) scaleP4_kernel() {
    int gw = (blockIdx.x * blockDim.x + threadIdx.x) >> 5;
    int lane = threadIdx.x & 31;
    if (gw >= N_NODES || lane >= 25) return;
    float di = __ldg(&g_dinv[gw]);
    float2 p = __ldg((const float2*)(g_P + ((size_t)4 * N_NODES + gw) * STRIDE) + lane);
    g_P4s[(size_t)gw * HSTRIDE + lane] = __floats2half2_rn(di * p.x, di * p.y);
}

// ---------------- f32x2 helpers ----------------
__device__ __forceinline__ unsigned long long pack2(float lo, float hi) {
    unsigned long long r;
    asm("mov.b64 %0, {%1, %2};" : "=l"(r) : "f"(lo), "f"(hi));
    return r;
}
__device__ __forceinline__ void unpack2(unsigned long long v, float& lo, float& hi) {
    asm("mov.b64 {%0, %1}, %2;" : "=f"(lo), "=f"(hi) : "l"(v));
}
#define FMA2(acc, a, b) asm("fma.rn.f32x2 %0, %1, %2, %0;" : "+l"(acc) : "l"(a), "l"(b))

// ---------------- projection: P_k = x @ W_k (fp32 out), 2 nodes/thread -----------
__global__ void __launch_bounds__(128) proj_kernel(const float* __restrict__ x,
                                                   const float* __restrict__ cheb_w,
                                                   int k_offset) {
    __shared__ __align__(16) float Wsm[D_IN * 52];
    int tid = threadIdx.x;
    int k = blockIdx.y + k_offset;
    const float* W = cheb_w + (size_t)k * D_IN * D_HID;
    #pragma unroll 1
    for (int o = 0; o < D_HID; o++) Wsm[tid * 52 + o] = W[tid * D_HID + o];
    Wsm[tid * 52 + 50] = 0.0f;
    Wsm[tid * 52 + 51] = 0.0f;
    __syncthreads();

    int n0 = blockIdx.x * 256 + tid;
    int n1 = n0 + 128;
    bool v0 = n0 < N_NODES;
    bool v1 = n1 < N_NODES;

    unsigned long long acc0[26], acc1[26];
    #pragma unroll
    for (int p = 0; p < 26; p++) { acc0[p] = 0ull; acc1[p] = 0ull; }

    const float4* A0 = (const float4*)(x + (size_t)n0 * D_IN);
    const float4* A1 = (const float4*)(x + (size_t)n1 * D_IN);
    float4 z4 = make_float4(0.f, 0.f, 0.f, 0.f);
    float4 a0 = v0 ? __ldg(A0) : z4;
    float4 a1 = v1 ? __ldg(A1) : z4;

    #pragma unroll 1
    for (int ic = 0; ic < 32; ic++) {
        float4 a0n = z4, a1n = z4;
        if (ic < 31) {
            if (v0) a0n = __ldg(A0 + ic + 1);
            if (v1) a1n = __ldg(A1 + ic + 1);
        }
        float av0[4] = {a0.x, a0.y, a0.z, a0.w};
        float av1[4] = {a1.x, a1.y, a1.z, a1.w};
        #pragma unroll
        for (int j = 0; j < 4; j++) {
            unsigned long long a0p = pack2(av0[j], av0[j]);
            unsigned long long a1p = pack2(av1[j], av1[j]);
            const float4* wrow = (const float4*)(Wsm + (ic * 4 + j) * 52);
            #pragma unroll
            for (int q = 0; q < 13; q++) {
                float4 wv = wrow[q];
                unsigned long long w01 = pack2(wv.x, wv.y);
                unsigned long long w23 = pack2(wv.z, wv.w);
                FMA2(acc0[2 * q],     w01, a0p);
                FMA2(acc0[2 * q + 1], w23, a0p);
                FMA2(acc1[2 * q],     w01, a1p);
                FMA2(acc1[2 * q + 1], w23, a1p);
            }
        }
        a0 = a0n; a1 = a1n;
    }

    #pragma unroll
    for (int which = 0; which < 2; which++) {
        bool v = which ? v1 : v0;
        int n = which ? n1 : n0;
        unsigned long long* acc = which ? acc1 : acc0;
        if (!v) continue;
        float* dst = g_P + ((size_t)k * N_NODES + n) * STRIDE;
        #pragma unroll
        for (int q = 0; q < 12; q++) {
            float x0, x1, x2, x3;
            unpack2(acc[2 * q], x0, x1);
            unpack2(acc[2 * q + 1], x2, x3);
            ((float4*)dst)[q] = make_float4(x0, x1, x2, x3);
        }
        float x0, x1; unpack2(acc[24], x0, x1);
        ((float2*)dst)[24] = make_float2(x0, x1);
    }
}

// ---------------- weightless gather accumulate: uint16 bucket, aligned bursts -----
__device__ __forceinline__ void row_sum_h(const __half2* __restrict__ src,
                                          const unsigned short* __restrict__ row,
                                          int deg, bool act, int lane,
                                          float& Sx, float& Sy) {
    float ax0 = 0.f, ay0 = 0.f, ax1 = 0.f, ay1 = 0.f;
    int i = 0;
    #pragma unroll 1
    for (; i + 8 <= deg; i += 8) {
        uint4 cp = __ldg((const uint4*)(row + i));       // 8 cols, 16B aligned
        unsigned c[8];
        c[0] = cp.x & 0xffffu; c[1] = cp.x >> 16;
        c[2] = cp.y & 0xffffu; c[3] = cp.y >> 16;
        c[4] = cp.z & 0xffffu; c[5] = cp.z >> 16;
        c[6] = cp.w & 0xffffu; c[7] = cp.w >> 16;
        if (act) {
            __half2 v[8];
            #pragma unroll
            for (int u = 0; u < 8; u++)
                v[u] = __ldcg((__half2*)(src + (size_t)c[u] * HSTRIDE + lane));
            #pragma unroll
            for (int u = 0; u < 8; u++) {
                float2 vf = __half22float2(v[u]);
                if (u & 1) { ax1 += vf.x; ay1 += vf.y; }
                else       { ax0 += vf.x; ay0 += vf.y; }
            }
        }
    }
    if (deg - i >= 4) {
        uint2 cp = __ldg((const uint2*)(row + i));       // 8B aligned
        unsigned c[4];
        c[0] = cp.x & 0xffffu; c[1] = cp.x >> 16;
        c[2] = cp.y & 0xffffu; c[3] = cp.y >> 16;
        if (act) {
            #pragma unroll
            for (int u = 0; u < 4; u++) {
                float2 vf = __half22float2(
                    __ldcg((__half2*)(src + (size_t)c[u] * HSTRIDE + lane)));
                if (u & 1) { ax1 += vf.x; ay1 += vf.y; }
                else       { ax0 += vf.x; ay0 += vf.y; }
            }
        }
        i += 4;
    }
    if (deg - i >= 2) {
        unsigned cp = __ldg((const unsigned*)(row + i)); // 4B aligned
        unsigned c0 = cp & 0xffffu, c1 = cp >> 16;
        if (act) {
            float2 v0 = __half22float2(__ldcg((__half2*)(src + (size_t)c0 * HSTRIDE + lane)));
            float2 v1 = __half22float2(__ldcg((__half2*)(src + (size_t)c1 * HSTRIDE + lane)));
            ax0 += v0.x; ay0 += v0.y;
            ax1 += v1.x; ay1 += v1.y;
        }
        i += 2;
    }
    if (i < deg) {
        unsigned c = __ldg(row + i);
        if (act) {
            float2 v = __half22float2(__ldcg((__half2*)(src + (size_t)c * HSTRIDE + lane)));
            ax0 += v.x; ay0 += v.y;
        }
    }
    Sx = ax0 + ax1;
    Sy = ay0 + ay1;
}

// ---------------- Clenshaw prop: real = P - scale*dinv*S - sub; scaled = dinv*real
__global__ void __launch_bounds__(256) prop_b(const __half2* __restrict__ src,
                                              const float* __restrict__ P,
                                              const __half2* __restrict__ subH,
                                              const float* __restrict__ subF,
                                              float scale,
                                              __half2* __restrict__ dstR,
                                              __half2* __restrict__ dstS) {
    int gw = (blockIdx.x * blockDim.x + threadIdx.x) >> 5;
    int lane = threadIdx.x & 31;
    if (gw >= N_NODES) return;
    int deg = __ldg(&g_cursor[gw]);
    if (deg > CAP) deg = CAP;
    const unsigned short* row = g_bucket + (size_t)gw * CAP;
    const bool act = lane < 25;
    float Sx, Sy;
    row_sum_h(src, row, deg, act, lane, Sx, Sy);

    if (act) {
        float di = __ldg(&g_dinv[gw]);
        float2 p = __ldg((const float2*)P + (size_t)gw * (STRIDE / 2) + lane);
        float sdi = scale * di;
        float rx = p.x - sdi * Sx;
        float ry = p.y - sdi * Sy;
        if (subH) {
            float2 sb = __half22float2(__ldg(subH + (size_t)gw * HSTRIDE + lane));
            rx -= sb.x; ry -= sb.y;
        }
        if (subF) {
            float2 sb = __ldg((const float2*)subF + (size_t)gw * (STRIDE / 2) + lane);
            rx -= sb.x; ry -= sb.y;
        }
        size_t off = (size_t)gw * HSTRIDE + lane;
        if (dstR) dstR[off] = __floats2half2_rn(rx, ry);
        dstS[off] = __floats2half2_rn(di * rx, di * ry);
    }
}

// ---------------- last prop fused with head ----------------
__global__ void __launch_bounds__(256) prop_head(const __half2* __restrict__ src,
                                                 const float* __restrict__ P,
                                                 const __half2* __restrict__ subH,
                                                 const float* __restrict__ cheb_b,
                                                 const float* __restrict__ fc_w,
                                                 const float* __restrict__ fc_b,
                                                 float* __restrict__ out) {
    __shared__ __align__(8) float s_fcwT[D_OUT * 52];
    __shared__ float s_b[D_HID];
    __shared__ float s_fcb[D_OUT];
    int tid = threadIdx.x;
    for (int i = tid; i < D_HID * D_OUT; i += blockDim.x) {
        int j = i / D_OUT, o = i % D_OUT;
        s_fcwT[o * 52 + j] = fc_w[i];
    }
    if (tid < D_OUT) { s_fcwT[tid * 52 + 50] = 0.f; s_fcwT[tid * 52 + 51] = 0.f; }
    if (tid < D_HID) s_b[tid] = cheb_b[tid];
    if (tid < D_OUT) s_fcb[tid] = fc_b[tid];
    __syncthreads();

    int gw = (blockIdx.x * blockDim.x + tid) >> 5;
    int lane = tid & 31;
    if (gw >= N_NODES) return;
    int deg = __ldg(&g_cursor[gw]);
    if (deg > CAP) deg = CAP;
    const unsigned short* row = g_bucket + (size_t)gw * CAP;
    const bool act = lane < 25;
    float Sx, Sy;
    row_sum_h(src, row, deg, act, lane, Sx, Sy);

    float l[D_OUT];
    if (act) {
        float di = __ldg(&g_dinv[gw]);
        float2 p  = __ldg((const float2*)P + (size_t)gw * (STRIDE / 2) + lane);
        float2 sb = __half22float2(__ldg(subH + (size_t)gw * HSTRIDE + lane));
        float hx = fmaxf(p.x - di * Sx - sb.x + s_b[2 * lane],     0.0f);  // scale = 1
        float hy = fmaxf(p.y - di * Sy - sb.y + s_b[2 * lane + 1], 0.0f);
        #pragma unroll
        for (int o = 0; o < D_OUT; o++) {
            float2 w2 = ((const float2*)(s_fcwT + o * 52))[lane];
            l[o] = hx * w2.x + hy * w2.y;
        }
    } else {
        #pragma unroll
        for (int o = 0; o < D_OUT; o++) l[o] = 0.0f;
    }

    #pragma unroll
    for (int offm = 16; offm > 0; offm >>= 1) {
        #pragma unroll
        for (int o = 0; o < D_OUT; o++)
            l[o] += __shfl_xor_sync(0xffffffffu, l[o], offm);
    }

    if (lane == 0) {
        #pragma unroll
        for (int o = 0; o < D_OUT; o++) l[o] += s_fcb[o];
        float m = l[0];
        #pragma unroll
        for (int o = 1; o < D_OUT; o++) m = fmaxf(m, l[o]);
        float ssum = 0.0f;
        #pragma unroll
        for (int o = 0; o < D_OUT; o++) ssum += expf(l[o] - m);
        float lse = m + logf(ssum);
        float* orow = out + (size_t)gw * D_OUT;
        #pragma unroll
        for (int o = 0; o < D_OUT; o++) orow[o] = l[o] - lse;
    }
}

// ---------------- launch ----------------
extern "C" void kernel_launch(void* const* d_in, const int* in_sizes, int n_in,
                              void* d_out, int out_size) {
    const float* x      = (const float*)d_in[0];
    const void*  ei     = d_in[1];
    const float* cheb_w = (const float*)d_in[2];
    const float* cheb_b = (const float*)d_in[3];
    const float* fc_w   = (const float*)d_in[4];
    const float* fc_b   = (const float*)d_in[5];
    float* out = (float*)d_out;

    float* P;
    __half2 *P4s, *b3s, *b3r, *b2s, *b2r, *b1s;
    cudaGetSymbolAddress((void**)&P,   g_P);
    cudaGetSymbolAddress((void**)&P4s, g_P4s);
    cudaGetSymbolAddress((void**)&b3s, g_b3s);
    cudaGetSymbolAddress((void**)&b3r, g_b3r);
    cudaGetSymbolAddress((void**)&b2s, g_b2s);
    cudaGetSymbolAddress((void**)&b2r, g_b2r);
    cudaGetSymbolAddress((void**)&b1s, g_b1s);
    const size_t PS = (size_t)N_NODES * STRIDE;
    float* P0 = P + 0 * PS;
    float* P1 = P + 1 * PS;
    float* P2 = P + 2 * PS;
    float* P3 = P + 3 * PS;
    float* P4 = P + 4 * PS;

    const int TB = 256;
    const int NODE_BLK = (N_NODES + TB - 1) / TB;
    const int HALF_EDGE_BLK = (N_EDGES / 2 + TB - 1) / TB;
    const long long PT = (long long)N_NODES * 32;
    const int PROP_BLK = (int)((PT + TB - 1) / TB);
    const int PROJ_GX = (N_NODES + 255) / 256;   // 196 blocks, 2 nodes/thread

    static cudaStream_t s_proj = nullptr;
    static cudaEvent_t evA = nullptr, ev2 = nullptr, ev1 = nullptr, ev0 = nullptr, ev_fork = nullptr;
    static int use_async = -1;
    if (use_async < 0) {
        bool ok = (cudaStreamCreateWithFlags(&s_proj, cudaStreamNonBlocking) == cudaSuccess);
        ok = ok && (cudaEventCreateWithFlags(&ev_fork, cudaEventDisableTiming) == cudaSuccess);
        ok = ok && (cudaEventCreateWithFlags(&evA, cudaEventDisableTiming) == cudaSuccess);
        ok = ok && (cudaEventCreateWithFlags(&ev2, cudaEventDisableTiming) == cudaSuccess);
        ok = ok && (cudaEventCreateWithFlags(&ev1, cudaEventDisableTiming) == cudaSuccess);
        ok = ok && (cudaEventCreateWithFlags(&ev0, cudaEventDisableTiming) == cudaSuccess);
        use_async = ok ? 1 : 0;
    }

    if (use_async) {
        // ---- fork: pipelined projections on side stream ----
        cudaEventRecord(ev_fork, 0);
        cudaStreamWaitEvent(s_proj, ev_fork, 0);
        proj_kernel<<<dim3(PROJ_GX, 2), 128, 0, s_proj>>>(x, cheb_w, 3);  // k=3,4
        cudaEventRecord(evA, s_proj);
        proj_kernel<<<dim3(PROJ_GX, 1), 128, 0, s_proj>>>(x, cheb_w, 2);  // k=2
        cudaEventRecord(ev2, s_proj);
        proj_kernel<<<dim3(PROJ_GX, 1), 128, 0, s_proj>>>(x, cheb_w, 1);  // k=1
        cudaEventRecord(ev1, s_proj);
        proj_kernel<<<dim3(PROJ_GX, 1), 128, 0, s_proj>>>(x, cheb_w, 0);  // k=0
        cudaEventRecord(ev0, s_proj);

        // ---- single-pass bucket CSR (main stream, concurrent) ----
        init_kernel<<<NODE_BLK, TB>>>((const int*)ei);
        scatter_kernel<<<HALF_EDGE_BLK, TB>>>(ei);
        dinv_kernel<<<NODE_BLK, TB>>>();

        // ---- Clenshaw ----
        cudaStreamWaitEvent(0, evA, 0);
        scaleP4_kernel<<<PROP_BLK, TB>>>();                                   // P4s = D P4
        prop_b<<<PROP_BLK, TB>>>(P4s, P3, nullptr, nullptr, 2.0f, b3r, b3s);  // b3 = P3 + 2L P4
        cudaStreamWaitEvent(0, ev2, 0);
        prop_b<<<PROP_BLK, TB>>>(b3s, P2, nullptr, P4,      2.0f, b2r, b2s);  // b2 = P2 + 2L b3 - P4
        cudaStreamWaitEvent(0, ev1, 0);
        prop_b<<<PROP_BLK, TB>>>(b2s, P1, b3r,    nullptr,  2.0f, nullptr, b1s); // b1 = P1 + 2L b2 - b3
        cudaStreamWaitEvent(0, ev0, 0);
        prop_head<<<PROP_BLK, TB>>>(b1s, P0, b2r, cheb_b, fc_w, fc_b, out);
    } else {
        // serial fallback
        init_kernel<<<NODE_BLK, TB>>>((const int*)ei);
        scatter_kernel<<<HALF_EDGE_BLK, TB>>>(ei);
        dinv_kernel<<<NODE_BLK, TB>>>();
        proj_kernel<<<dim3(PROJ_GX, 5), 128>>>(x, cheb_w, 0);
        scaleP4_kernel<<<PROP_BLK, TB>>>();
        prop_b<<<PROP_BLK, TB>>>(P4s, P3, nullptr, nullptr, 2.0f, b3r, b3s);
        prop_b<<<PROP_BLK, TB>>>(b3s, P2, nullptr, P4,      2.0f, b2r, b2s);
        prop_b<<<PROP_BLK, TB>>>(b2s, P1, b3r,    nullptr,  2.0f, nullptr, b1s);
        prop_head<<<PROP_BLK, TB>>>(b1s, P0, b2r, cheb_b, fc_w, fc_b, out);
    }
}